// round 1
// baseline (speedup 1.0000x reference)
#include <cuda_runtime.h>
#include <math.h>

#define N_NODES 4096
#define E_EDGES 131072
#define EN_EDGES (E_EDGES + N_NODES)
#define D_INP 128
#define D_MODEL 256
#define H_HEADS 8
#define D_HEAD 32
#define FF_DIM 2048
#define B_PAIRS 16384

// ---------------- scratch (device globals; allocation-free) ----------------
__device__ __align__(256) float g_h[N_NODES * D_MODEL];
__device__ __align__(256) float g_qkv[N_NODES * 3 * D_MODEL];
__device__ __align__(256) float g_ctx[N_NODES * D_MODEL];
__device__ __align__(256) float g_tmp[N_NODES * D_MODEL];
__device__ __align__(256) float g_h1[N_NODES * D_MODEL];
__device__ __align__(256) float g_ff[N_NODES * FF_DIM];
__device__ __align__(256) float g_h2[N_NODES * D_MODEL];
__device__ __align__(256) float g_hw[N_NODES * H_HEADS * D_MODEL];
__device__ __align__(256) float g_asrc[N_NODES * H_HEADS];
__device__ __align__(256) float g_adst[N_NODES * H_HEADS];
__device__ __align__(256) float g_hg[N_NODES * D_MODEL];
__device__ int g_deg[N_NODES];
__device__ int g_off[N_NODES + 1];
__device__ int g_cursor[N_NODES];
__device__ int g_csrc[EN_EDGES];

// ---------------- generic tiled SGEMM: C[M,N] = A[M,K] @ B[K,N] (+bias, +relu)
template <int RELU>
__global__ __launch_bounds__(256) void sgemm64(
    const float* __restrict__ A, const float* __restrict__ B,
    const float* __restrict__ bias, float* __restrict__ C,
    int M, int Nn, int K) {
  __shared__ float As[16][64];
  __shared__ float Bs[16][64];
  int tid = threadIdx.x;
  int bm = blockIdx.y * 64, bn = blockIdx.x * 64;
  int tx = tid & 15, ty = tid >> 4;

  float acc[4][4];
#pragma unroll
  for (int i = 0; i < 4; i++)
#pragma unroll
    for (int j = 0; j < 4; j++) acc[i][j] = 0.f;

  int ra = tid >> 2, ca = (tid & 3) * 4;  // A tile loader: row 0..63, 4 cols
  int rb = tid >> 4, cb = (tid & 15) * 4; // B tile loader: row 0..15, 4 cols

  for (int k0 = 0; k0 < K; k0 += 16) {
    float4 av = *(const float4*)(A + (size_t)(bm + ra) * K + k0 + ca);
    As[ca + 0][ra] = av.x;
    As[ca + 1][ra] = av.y;
    As[ca + 2][ra] = av.z;
    As[ca + 3][ra] = av.w;
    float4 bv = *(const float4*)(B + (size_t)(k0 + rb) * Nn + bn + cb);
    *(float4*)&Bs[rb][cb] = bv;
    __syncthreads();
#pragma unroll
    for (int k = 0; k < 16; k++) {
      float4 a = *(const float4*)&As[k][ty * 4];
      float4 b = *(const float4*)&Bs[k][tx * 4];
      acc[0][0] += a.x * b.x; acc[0][1] += a.x * b.y; acc[0][2] += a.x * b.z; acc[0][3] += a.x * b.w;
      acc[1][0] += a.y * b.x; acc[1][1] += a.y * b.y; acc[1][2] += a.y * b.z; acc[1][3] += a.y * b.w;
      acc[2][0] += a.z * b.x; acc[2][1] += a.z * b.y; acc[2][2] += a.z * b.z; acc[2][3] += a.z * b.w;
      acc[3][0] += a.w * b.x; acc[3][1] += a.w * b.y; acc[3][2] += a.w * b.z; acc[3][3] += a.w * b.w;
    }
    __syncthreads();
  }
#pragma unroll
  for (int i = 0; i < 4; i++) {
    float4 o;
    float bx = bias ? bias[bn + tx * 4 + 0] : 0.f;
    float by = bias ? bias[bn + tx * 4 + 1] : 0.f;
    float bz = bias ? bias[bn + tx * 4 + 2] : 0.f;
    float bw = bias ? bias[bn + tx * 4 + 3] : 0.f;
    o.x = acc[i][0] + bx; o.y = acc[i][1] + by; o.z = acc[i][2] + bz; o.w = acc[i][3] + bw;
    if (RELU) {
      o.x = fmaxf(o.x, 0.f); o.y = fmaxf(o.y, 0.f);
      o.z = fmaxf(o.z, 0.f); o.w = fmaxf(o.w, 0.f);
    }
    *(float4*)(C + (size_t)(bm + ty * 4 + i) * Nn + bn + tx * 4) = o;
  }
}

// ---------------- flash attention (fp32, online softmax) ----------------
// grid: (N/32, H). block: 256 threads = 32 q-rows x 8 lanes.
__global__ __launch_bounds__(256) void attn_kernel() {
  __shared__ float Qs[32][32];
  __shared__ float Ks[64][36];
  __shared__ float Vs[64][36];
  __shared__ float Ps[32][65];
  int tid = threadIdx.x;
  int h = blockIdx.y;
  int qb = blockIdx.x * 32;

  {
    int r = tid >> 3, c4 = (tid & 7) * 4;
    *(float4*)&Qs[r][c4] =
        *(const float4*)(g_qkv + (size_t)(qb + r) * 768 + h * 32 + c4);
  }
  __syncthreads();

  int qi = tid >> 3, g = tid & 7;
  float q[32];
#pragma unroll
  for (int i = 0; i < 8; i++) {
    float4 t = *(const float4*)&Qs[qi][i * 4];
    q[4 * i] = t.x; q[4 * i + 1] = t.y; q[4 * i + 2] = t.z; q[4 * i + 3] = t.w;
  }

  const float scale = 0.17677669529663687f;  // 1/sqrt(32)
  float m = -1e30f, Z = 0.f;
  float acc0 = 0.f, acc1 = 0.f, acc2 = 0.f, acc3 = 0.f;

  for (int kt = 0; kt < N_NODES; kt += 64) {
#pragma unroll
    for (int j = 0; j < 2; j++) {
      int idx = tid + j * 256;
      int r = idx >> 3, c4 = (idx & 7) * 4;
      *(float4*)&Ks[r][c4] =
          *(const float4*)(g_qkv + (size_t)(kt + r) * 768 + 256 + h * 32 + c4);
      *(float4*)&Vs[r][c4] =
          *(const float4*)(g_qkv + (size_t)(kt + r) * 768 + 512 + h * 32 + c4);
    }
    __syncthreads();

    float s[8];
    float tmax = -1e30f;
#pragma unroll
    for (int kk = 0; kk < 8; kk++) {
      const float* kr = &Ks[g * 8 + kk][0];
      float d = 0.f;
#pragma unroll
      for (int i = 0; i < 8; i++) {
        float4 kv = *(const float4*)&kr[4 * i];
        d += q[4 * i] * kv.x + q[4 * i + 1] * kv.y + q[4 * i + 2] * kv.z +
             q[4 * i + 3] * kv.w;
      }
      s[kk] = d * scale;
      tmax = fmaxf(tmax, s[kk]);
    }
#pragma unroll
    for (int o = 1; o < 8; o <<= 1)
      tmax = fmaxf(tmax, __shfl_xor_sync(0xffffffffu, tmax, o));
    float mnew = fmaxf(m, tmax);
    float fac = __expf(m - mnew);
    float lsum = 0.f;
#pragma unroll
    for (int kk = 0; kk < 8; kk++) {
      float p = __expf(s[kk] - mnew);
      Ps[qi][g * 8 + kk] = p;
      lsum += p;
    }
#pragma unroll
    for (int o = 1; o < 8; o <<= 1)
      lsum += __shfl_xor_sync(0xffffffffu, lsum, o);
    Z = Z * fac + lsum;
    m = mnew;
    acc0 *= fac; acc1 *= fac; acc2 *= fac; acc3 *= fac;
    __syncwarp();

    int d0 = g * 4;
#pragma unroll 8
    for (int key = 0; key < 64; key++) {
      float p = Ps[qi][key];
      float4 v = *(const float4*)&Vs[key][d0];
      acc0 += p * v.x; acc1 += p * v.y; acc2 += p * v.z; acc3 += p * v.w;
    }
    __syncthreads();
  }
  float inv = 1.f / Z;
  float4 o = {acc0 * inv, acc1 * inv, acc2 * inv, acc3 * inv};
  *(float4*)(g_ctx + (size_t)(qb + qi) * 256 + h * 32 + g * 4) = o;
}

// ---------------- residual + LayerNorm: out = LN(a+b)*g+beta ----------------
__global__ __launch_bounds__(256) void ln_res(const float* __restrict__ a,
                                              const float* __restrict__ b,
                                              const float* __restrict__ gam,
                                              const float* __restrict__ bet,
                                              float* __restrict__ out) {
  int w = threadIdx.x >> 5, lane = threadIdx.x & 31;
  int row = blockIdx.x * 8 + w;
  float x[8];
  float s = 0.f;
#pragma unroll
  for (int i = 0; i < 8; i++) {
    int d = lane + i * 32;
    x[i] = a[(size_t)row * 256 + d] + b[(size_t)row * 256 + d];
    s += x[i];
  }
#pragma unroll
  for (int o = 16; o; o >>= 1) s += __shfl_xor_sync(0xffffffffu, s, o);
  float mean = s * (1.f / 256.f);
  float v = 0.f;
#pragma unroll
  for (int i = 0; i < 8; i++) {
    float t = x[i] - mean;
    v += t * t;
  }
#pragma unroll
  for (int o = 16; o; o >>= 1) v += __shfl_xor_sync(0xffffffffu, v, o);
  float r = rsqrtf(v * (1.f / 256.f) + 1e-5f);
#pragma unroll
  for (int i = 0; i < 8; i++) {
    int d = lane + i * 32;
    out[(size_t)row * 256 + d] = (x[i] - mean) * r * gam[d] + bet[d];
  }
}

// ---------------- GAT attention dot products ----------------
__global__ __launch_bounds__(256) void gat_dots(const float* __restrict__ att_src,
                                                const float* __restrict__ att_dst) {
  int n = blockIdx.x;
  int w = threadIdx.x >> 5, lane = threadIdx.x & 31;
  const float* row = g_hw + (size_t)n * 2048 + w * 256;
  float s1 = 0.f, s2 = 0.f;
#pragma unroll
  for (int i = 0; i < 8; i++) {
    int d = lane + i * 32;
    float v = row[d];
    s1 += v * att_src[w * 256 + d];
    s2 += v * att_dst[w * 256 + d];
  }
#pragma unroll
  for (int o = 16; o; o >>= 1) {
    s1 += __shfl_xor_sync(0xffffffffu, s1, o);
    s2 += __shfl_xor_sync(0xffffffffu, s2, o);
  }
  if (!lane) {
    g_asrc[n * 8 + w] = s1;
    g_adst[n * 8 + w] = s2;
  }
}

// ---------------- CSR build ----------------
__global__ void csr_zero() {
  int i = blockIdx.x * 256 + threadIdx.x;
  if (i < N_NODES) g_deg[i] = 0;
}
__global__ void csr_count(const int* __restrict__ ei) {
  int i = blockIdx.x * 256 + threadIdx.x;
  if (i >= EN_EDGES) return;
  int d = (i < E_EDGES) ? ei[E_EDGES + i] : (i - E_EDGES);
  atomicAdd(&g_deg[d], 1);
}
__global__ __launch_bounds__(1024) void csr_scan() {
  __shared__ int s[1024];
  int tid = threadIdx.x;
  int v0 = g_deg[tid * 4 + 0], v1 = g_deg[tid * 4 + 1];
  int v2 = g_deg[tid * 4 + 2], v3 = g_deg[tid * 4 + 3];
  int tsum = v0 + v1 + v2 + v3;
  s[tid] = tsum;
  __syncthreads();
  for (int o = 1; o < 1024; o <<= 1) {
    int t = (tid >= o) ? s[tid - o] : 0;
    __syncthreads();
    s[tid] += t;
    __syncthreads();
  }
  int excl = tid ? s[tid - 1] : 0;
  int o0 = excl, o1 = o0 + v0, o2 = o1 + v1, o3 = o2 + v2;
  g_off[tid * 4 + 0] = o0; g_cursor[tid * 4 + 0] = o0;
  g_off[tid * 4 + 1] = o1; g_cursor[tid * 4 + 1] = o1;
  g_off[tid * 4 + 2] = o2; g_cursor[tid * 4 + 2] = o2;
  g_off[tid * 4 + 3] = o3; g_cursor[tid * 4 + 3] = o3;
  if (tid == 1023) g_off[N_NODES] = excl + tsum;
}
__global__ void csr_fill(const int* __restrict__ ei) {
  int i = blockIdx.x * 256 + threadIdx.x;
  if (i >= EN_EDGES) return;
  int srcv = (i < E_EDGES) ? ei[i] : (i - E_EDGES);
  int dstv = (i < E_EDGES) ? ei[E_EDGES + i] : (i - E_EDGES);
  int pos = atomicAdd(&g_cursor[dstv], 1);
  g_csrc[pos] = srcv;
}

// ---------------- GAT aggregation: one block per destination node ----------
__global__ __launch_bounds__(256) void gat_agg(const float* __restrict__ gat_bias) {
  int n = blockIdx.x, tid = threadIdx.x;
  __shared__ int ssrc[256];
  __shared__ float se[256 * 8];
  __shared__ float sm[8], sz[8], sfac[8], sadst[8];
  __shared__ float sred[8 * 32];

  int start = g_off[n], end = g_off[n + 1];
  if (tid < 8) {
    sm[tid] = -1e30f;
    sz[tid] = 0.f;
    sadst[tid] = g_adst[n * 8 + tid];
  }
  float acc[8];
#pragma unroll
  for (int i = 0; i < 8; i++) acc[i] = 0.f;
  __syncthreads();

  for (int cs = start; cs < end; cs += 256) {
    int cnt = min(256, end - cs);
    if (tid < cnt) ssrc[tid] = g_csrc[cs + tid];
    __syncthreads();
    // e = leaky_relu(a_src[src] + a_dst[n])
#pragma unroll
    for (int j = 0; j < 8; j++) {
      int idx = tid + j * 256;
      int eidx = idx >> 3, hh = idx & 7;
      if (eidx < cnt) {
        float v = g_asrc[ssrc[eidx] * 8 + hh] + sadst[hh];
        se[idx] = (v > 0.f) ? v : 0.2f * v;
      }
    }
    __syncthreads();
    // chunk max per head
    int h = tid & 7, gg = tid >> 3;
    float mx = -1e30f;
    for (int e = gg; e < cnt; e += 32) mx = fmaxf(mx, se[e * 8 + h]);
    sred[h * 32 + gg] = mx;
    __syncthreads();
    if (tid < 8) {
      float m2 = -1e30f;
      for (int g2 = 0; g2 < 32; g2++) m2 = fmaxf(m2, sred[tid * 32 + g2]);
      float mold = sm[tid];
      float mnew = fmaxf(mold, m2);
      sfac[tid] = __expf(mold - mnew);
      sm[tid] = mnew;
      sz[tid] *= sfac[tid];
    }
    __syncthreads();
#pragma unroll
    for (int i = 0; i < 8; i++) acc[i] *= sfac[i];
    // p = exp(e - m), chunk sum per head
    float sum = 0.f;
    for (int e = gg; e < cnt; e += 32) {
      float p = __expf(se[e * 8 + h] - sm[h]);
      se[e * 8 + h] = p;
      sum += p;
    }
    sred[h * 32 + gg] = sum;
    __syncthreads();
    if (tid < 8) {
      float s2 = 0.f;
      for (int g2 = 0; g2 < 32; g2++) s2 += sred[tid * 32 + g2];
      sz[tid] += s2;
    }
    __syncthreads();
    // accumulate: acc[h] += p[e][h] * hw[src][h][tid]
    for (int e = 0; e < cnt; e++) {
      const float* row = g_hw + (size_t)ssrc[e] * 2048;
#pragma unroll
      for (int hh = 0; hh < 8; hh++)
        acc[hh] += se[e * 8 + hh] * row[hh * 256 + tid];
    }
    __syncthreads();
  }
  float r = 0.f;
#pragma unroll
  for (int hh = 0; hh < 8; hh++) r += acc[hh] / (sz[hh] + 1e-16f);
  g_hg[(size_t)n * 256 + tid] = r * 0.125f + gat_bias[tid];
}

// ---------------- fused classifier: gather + GEMM1 + relu + GEMM2 + sigmoid
__global__ __launch_bounds__(256) void classify(
    const float* __restrict__ w1, const float* __restrict__ b1,
    const float* __restrict__ w2, const float* __restrict__ b2,
    const int* __restrict__ iA, const int* __restrict__ iB,
    float* __restrict__ out) {
  __shared__ float sp[16][512];
  __shared__ int sia[16], sib[16];
  int tid = threadIdx.x;
  int bp = blockIdx.x * 16;
  if (tid < 16) sia[tid] = iA[bp + tid];
  else if (tid < 32) sib[tid - 16] = iB[bp + tid - 16];
  __syncthreads();
#pragma unroll
  for (int j = 0; j < 8; j++) {
    int idx4 = tid + j * 256;       // 0..2047 float4 slots
    int p = idx4 >> 7;              // 128 float4 per pair
    int c = (idx4 & 127) * 4;
    const float* src = (c < 256) ? (g_hg + (size_t)sia[p] * 256 + c)
                                 : (g_hg + (size_t)sib[p] * 256 + (c - 256));
    *(float4*)&sp[p][c] = *(const float4*)src;
  }
  __syncthreads();
  int p = tid >> 4;
  int j0 = (tid & 15) * 4;
  float a0 = 0.f, a1 = 0.f, a2 = 0.f, a3 = 0.f;
  for (int k = 0; k < 512; k++) {
    float s = sp[p][k];
    float4 w = *(const float4*)(w1 + (size_t)k * 64 + j0);
    a0 += s * w.x; a1 += s * w.y; a2 += s * w.z; a3 += s * w.w;
  }
  a0 = fmaxf(a0 + b1[j0 + 0], 0.f);
  a1 = fmaxf(a1 + b1[j0 + 1], 0.f);
  a2 = fmaxf(a2 + b1[j0 + 2], 0.f);
  a3 = fmaxf(a3 + b1[j0 + 3], 0.f);
  float part = a0 * w2[j0 + 0] + a1 * w2[j0 + 1] + a2 * w2[j0 + 2] + a3 * w2[j0 + 3];
#pragma unroll
  for (int o = 1; o < 16; o <<= 1) part += __shfl_xor_sync(0xffffffffu, part, o);
  if ((tid & 15) == 0) {
    float z = part + b2[0];
    out[bp + p] = 1.f / (1.f + __expf(-z));
  }
}

// ---------------- launch ----------------
extern "C" void kernel_launch(void* const* d_in, const int* in_sizes, int n_in,
                              void* d_out, int out_size) {
  const float* x = (const float*)d_in[0];
  const int* edge_index = (const int*)d_in[1];
  const int* idx_A = (const int*)d_in[2];
  const int* idx_B = (const int*)d_in[3];
  const float* w_in = (const float*)d_in[4];
  const float* b_in = (const float*)d_in[5];
  const float* w_qkv = (const float*)d_in[6];
  const float* b_qkv = (const float*)d_in[7];
  const float* w_o = (const float*)d_in[8];
  const float* b_o = (const float*)d_in[9];
  const float* ln1_g = (const float*)d_in[10];
  const float* ln1_b = (const float*)d_in[11];
  const float* w_ff1 = (const float*)d_in[12];
  const float* b_ff1 = (const float*)d_in[13];
  const float* w_ff2 = (const float*)d_in[14];
  const float* b_ff2 = (const float*)d_in[15];
  const float* ln2_g = (const float*)d_in[16];
  const float* ln2_b = (const float*)d_in[17];
  const float* gat_w = (const float*)d_in[18];
  const float* att_src = (const float*)d_in[19];
  const float* att_dst = (const float*)d_in[20];
  const float* gat_bias = (const float*)d_in[21];
  const float* cls_w1 = (const float*)d_in[22];
  const float* cls_b1 = (const float*)d_in[23];
  const float* cls_w2 = (const float*)d_in[24];
  const float* cls_b2 = (const float*)d_in[25];
  float* out = (float*)d_out;

  void* p;
  cudaGetSymbolAddress(&p, g_h);   float* ph = (float*)p;
  cudaGetSymbolAddress(&p, g_qkv); float* pqkv = (float*)p;
  cudaGetSymbolAddress(&p, g_ctx); float* pctx = (float*)p;
  cudaGetSymbolAddress(&p, g_tmp); float* ptmp = (float*)p;
  cudaGetSymbolAddress(&p, g_h1);  float* ph1 = (float*)p;
  cudaGetSymbolAddress(&p, g_ff);  float* pff = (float*)p;
  cudaGetSymbolAddress(&p, g_h2);  float* ph2 = (float*)p;
  cudaGetSymbolAddress(&p, g_hw);  float* phw = (float*)p;

  // 1. input projection: h = x @ w_in + b_in
  sgemm64<0><<<dim3(D_MODEL / 64, N_NODES / 64), 256>>>(x, w_in, b_in, ph,
                                                        N_NODES, D_MODEL, D_INP);
  // 2. qkv
  sgemm64<0><<<dim3(3 * D_MODEL / 64, N_NODES / 64), 256>>>(
      ph, w_qkv, b_qkv, pqkv, N_NODES, 3 * D_MODEL, D_MODEL);
  // 3. attention
  attn_kernel<<<dim3(N_NODES / 32, H_HEADS), 256>>>();
  // 4. ctx @ w_o + b_o
  sgemm64<0><<<dim3(D_MODEL / 64, N_NODES / 64), 256>>>(
      pctx, w_o, b_o, ptmp, N_NODES, D_MODEL, D_MODEL);
  // 5. LN1(h + attn_out)
  ln_res<<<N_NODES / 8, 256>>>(ph, ptmp, ln1_g, ln1_b, ph1);
  // 6. ff1 + relu
  sgemm64<1><<<dim3(FF_DIM / 64, N_NODES / 64), 256>>>(
      ph1, w_ff1, b_ff1, pff, N_NODES, FF_DIM, D_MODEL);
  // 7. ff2
  sgemm64<0><<<dim3(D_MODEL / 64, N_NODES / 64), 256>>>(
      pff, w_ff2, b_ff2, ptmp, N_NODES, D_MODEL, FF_DIM);
  // 8. LN2(h1 + ff)
  ln_res<<<N_NODES / 8, 256>>>(ph1, ptmp, ln2_g, ln2_b, ph2);
  // 9. GAT projection: hw = h2 @ gat_w
  sgemm64<0><<<dim3(H_HEADS * D_MODEL / 64, N_NODES / 64), 256>>>(
      ph2, gat_w, (const float*)nullptr, phw, N_NODES, H_HEADS * D_MODEL, D_MODEL);
  // 10. per-node attention logits
  gat_dots<<<N_NODES, 256>>>(att_src, att_dst);
  // 11. CSR by destination
  csr_zero<<<(N_NODES + 255) / 256, 256>>>();
  csr_count<<<(EN_EDGES + 255) / 256, 256>>>(edge_index);
  csr_scan<<<1, 1024>>>();
  csr_fill<<<(EN_EDGES + 255) / 256, 256>>>(edge_index);
  // 12. scatter-softmax aggregation -> hg
  gat_agg<<<N_NODES, 256>>>(gat_bias);
  // 13. fused pairwise classifier -> out
  classify<<<B_PAIRS / 16, 256>>>(cls_w1, cls_b1, cls_w2, cls_b2, idx_A, idx_B,
                                  out);
}

// round 2
// speedup vs baseline: 1.6425x; 1.6425x over previous
#include <cuda_runtime.h>
#include <math.h>
#include <stdint.h>

#define N_NODES 4096
#define E_EDGES 131072
#define EN_EDGES (E_EDGES + N_NODES)
#define D_INP 128
#define D_MODEL 256
#define H_HEADS 8
#define D_HEAD 32
#define FF_DIM 2048
#define B_PAIRS 16384

// ---------------- scratch (device globals; allocation-free) ----------------
__device__ __align__(256) float g_h[N_NODES * D_MODEL];
__device__ __align__(256) float g_qkv[N_NODES * 3 * D_MODEL];
__device__ __align__(256) float g_ctx[N_NODES * D_MODEL];
__device__ __align__(256) float g_tmp[N_NODES * D_MODEL];
__device__ __align__(256) float g_h1[N_NODES * D_MODEL];
__device__ __align__(256) float g_ff[N_NODES * FF_DIM];
__device__ __align__(256) float g_h2[N_NODES * D_MODEL];
__device__ __align__(256) float g_hw[N_NODES * H_HEADS * D_MODEL];
__device__ __align__(256) float g_asrc[N_NODES * H_HEADS];
__device__ __align__(256) float g_adst[N_NODES * H_HEADS];
__device__ __align__(256) float g_hg[N_NODES * D_MODEL];
__device__ int g_deg[N_NODES];
__device__ int g_off[N_NODES + 1];
__device__ int g_cursor[N_NODES];
__device__ int g_csrc[EN_EDGES];

// ---------------- TF32 helpers ----------------
__device__ __forceinline__ uint32_t f2tf32(float x) {
  uint32_t r;
  asm("cvt.rna.tf32.f32 %0, %1;" : "=r"(r) : "f"(x));
  return r;
}
__device__ __forceinline__ void mma_tf32(float* d, const uint32_t* a,
                                         const uint32_t* b) {
  asm volatile(
      "mma.sync.aligned.m16n8k8.row.col.f32.tf32.tf32.f32 "
      "{%0,%1,%2,%3}, {%4,%5,%6,%7}, {%8,%9}, {%0,%1,%2,%3};\n"
      : "+f"(d[0]), "+f"(d[1]), "+f"(d[2]), "+f"(d[3])
      : "r"(a[0]), "r"(a[1]), "r"(a[2]), "r"(a[3]), "r"(b[0]), "r"(b[1]));
}

// ---------------- TF32 tensor-core GEMM: C[M,N] = A[M,K] @ B[K,N] ----------
// Tile 128x64x16, 256 threads (8 warps: 4 along M x 2 along N), warp tile 32x32.
template <int RELU>
__global__ __launch_bounds__(256) void mma_gemm(
    const float* __restrict__ A, const float* __restrict__ B,
    const float* __restrict__ bias, float* __restrict__ C,
    int M, int Nn, int K) {
  __shared__ float As[128][20];  // padded: conflict-free frag reads, 16B aligned
  __shared__ float Bs[16][72];
  int tid = threadIdx.x;
  int warp = tid >> 5, lane = tid & 31;
  int gid = lane >> 2, tig = lane & 3;
  int bm = blockIdx.y * 128, bn = blockIdx.x * 64;
  int wm = (warp & 3) * 32;   // warp M offset
  int wn = (warp >> 2) * 32;  // warp N offset

  float acc[2][4][4];
#pragma unroll
  for (int t = 0; t < 2; t++)
#pragma unroll
    for (int u = 0; u < 4; u++)
#pragma unroll
      for (int i = 0; i < 4; i++) acc[t][u][i] = 0.f;

  int ar = tid >> 1, ac = (tid & 1) * 8;  // A loader: 128 rows x 16 cols
  int br = tid >> 4, bc = (tid & 15) * 4; // B loader: 16 rows x 64 cols

  for (int k0 = 0; k0 < K; k0 += 16) {
    float4 av0 = *(const float4*)(A + (size_t)(bm + ar) * K + k0 + ac);
    float4 av1 = *(const float4*)(A + (size_t)(bm + ar) * K + k0 + ac + 4);
    av0.x = __uint_as_float(f2tf32(av0.x));
    av0.y = __uint_as_float(f2tf32(av0.y));
    av0.z = __uint_as_float(f2tf32(av0.z));
    av0.w = __uint_as_float(f2tf32(av0.w));
    av1.x = __uint_as_float(f2tf32(av1.x));
    av1.y = __uint_as_float(f2tf32(av1.y));
    av1.z = __uint_as_float(f2tf32(av1.z));
    av1.w = __uint_as_float(f2tf32(av1.w));
    *(float4*)&As[ar][ac] = av0;
    *(float4*)&As[ar][ac + 4] = av1;
    float4 bv = *(const float4*)(B + (size_t)(k0 + br) * Nn + bn + bc);
    bv.x = __uint_as_float(f2tf32(bv.x));
    bv.y = __uint_as_float(f2tf32(bv.y));
    bv.z = __uint_as_float(f2tf32(bv.z));
    bv.w = __uint_as_float(f2tf32(bv.w));
    *(float4*)&Bs[br][bc] = bv;
    __syncthreads();

#pragma unroll
    for (int ks = 0; ks < 16; ks += 8) {
      uint32_t af[2][4], bf[4][2];
#pragma unroll
      for (int t = 0; t < 2; t++) {
        int row = wm + t * 16 + gid;
        af[t][0] = __float_as_uint(As[row][ks + tig]);
        af[t][1] = __float_as_uint(As[row + 8][ks + tig]);
        af[t][2] = __float_as_uint(As[row][ks + tig + 4]);
        af[t][3] = __float_as_uint(As[row + 8][ks + tig + 4]);
      }
#pragma unroll
      for (int u = 0; u < 4; u++) {
        int col = wn + u * 8 + gid;
        bf[u][0] = __float_as_uint(Bs[ks + tig][col]);
        bf[u][1] = __float_as_uint(Bs[ks + tig + 4][col]);
      }
#pragma unroll
      for (int t = 0; t < 2; t++)
#pragma unroll
        for (int u = 0; u < 4; u++) mma_tf32(acc[t][u], af[t], bf[u]);
    }
    __syncthreads();
  }

#pragma unroll
  for (int t = 0; t < 2; t++) {
#pragma unroll
    for (int u = 0; u < 4; u++) {
      int r = bm + wm + t * 16 + gid;
      int c = bn + wn + u * 8 + tig * 2;
      float b0 = bias ? bias[c] : 0.f;
      float b1 = bias ? bias[c + 1] : 0.f;
      float2 o0 = {acc[t][u][0] + b0, acc[t][u][1] + b1};
      float2 o1 = {acc[t][u][2] + b0, acc[t][u][3] + b1};
      if (RELU) {
        o0.x = fmaxf(o0.x, 0.f); o0.y = fmaxf(o0.y, 0.f);
        o1.x = fmaxf(o1.x, 0.f); o1.y = fmaxf(o1.y, 0.f);
      }
      *(float2*)(C + (size_t)r * Nn + c) = o0;
      *(float2*)(C + (size_t)(r + 8) * Nn + c) = o1;
    }
  }
}

// ---------------- flash attention (fp32, 2 queries/thread) ----------------
// grid: (N/64, H). block: 256 threads = 32 q-rows x 8 lanes; each thread
// handles queries (qi, qi+32) so each K/V smem read feeds 2 dot products.
__global__ __launch_bounds__(256) void attn_kernel() {
  __shared__ float Ks[64][36];
  __shared__ float Vs[64][36];
  __shared__ float Ps[64][65];
  int tid = threadIdx.x;
  int h = blockIdx.y;
  int qb = blockIdx.x * 64;
  int qi = tid >> 3, g = tid & 7;

  float q0[32], q1[32];
  {
    const float* qp0 = g_qkv + (size_t)(qb + qi) * 768 + h * 32;
    const float* qp1 = qp0 + (size_t)32 * 768;
#pragma unroll
    for (int i = 0; i < 8; i++) {
      float4 t0 = __ldg((const float4*)(qp0 + i * 4));
      float4 t1 = __ldg((const float4*)(qp1 + i * 4));
      q0[4 * i] = t0.x; q0[4 * i + 1] = t0.y; q0[4 * i + 2] = t0.z; q0[4 * i + 3] = t0.w;
      q1[4 * i] = t1.x; q1[4 * i + 1] = t1.y; q1[4 * i + 2] = t1.z; q1[4 * i + 3] = t1.w;
    }
  }

  const float scale = 0.17677669529663687f;  // 1/sqrt(32)
  float m0 = -1e30f, m1 = -1e30f, Z0 = 0.f, Z1 = 0.f;
  float a00 = 0.f, a01 = 0.f, a02 = 0.f, a03 = 0.f;
  float a10 = 0.f, a11 = 0.f, a12 = 0.f, a13 = 0.f;

  for (int kt = 0; kt < N_NODES; kt += 64) {
#pragma unroll
    for (int j = 0; j < 2; j++) {
      int idx = tid + j * 256;
      int r = idx >> 3, c4 = (idx & 7) * 4;
      *(float4*)&Ks[r][c4] =
          *(const float4*)(g_qkv + (size_t)(kt + r) * 768 + 256 + h * 32 + c4);
      *(float4*)&Vs[r][c4] =
          *(const float4*)(g_qkv + (size_t)(kt + r) * 768 + 512 + h * 32 + c4);
    }
    __syncthreads();

    float s0[8], s1[8];
    float t0 = -1e30f, t1 = -1e30f;
#pragma unroll
    for (int kk = 0; kk < 8; kk++) {
      const float* kr = &Ks[g * 8 + kk][0];
      float d0 = 0.f, d1 = 0.f;
#pragma unroll
      for (int i = 0; i < 8; i++) {
        float4 kv = *(const float4*)&kr[4 * i];
        d0 += q0[4 * i] * kv.x + q0[4 * i + 1] * kv.y + q0[4 * i + 2] * kv.z +
              q0[4 * i + 3] * kv.w;
        d1 += q1[4 * i] * kv.x + q1[4 * i + 1] * kv.y + q1[4 * i + 2] * kv.z +
              q1[4 * i + 3] * kv.w;
      }
      s0[kk] = d0 * scale; s1[kk] = d1 * scale;
      t0 = fmaxf(t0, s0[kk]); t1 = fmaxf(t1, s1[kk]);
    }
#pragma unroll
    for (int o = 1; o < 8; o <<= 1) {
      t0 = fmaxf(t0, __shfl_xor_sync(0xffffffffu, t0, o));
      t1 = fmaxf(t1, __shfl_xor_sync(0xffffffffu, t1, o));
    }
    float mn0 = fmaxf(m0, t0), mn1 = fmaxf(m1, t1);
    float f0 = __expf(m0 - mn0), f1 = __expf(m1 - mn1);
    float l0 = 0.f, l1 = 0.f;
#pragma unroll
    for (int kk = 0; kk < 8; kk++) {
      float p0 = __expf(s0[kk] - mn0);
      float p1 = __expf(s1[kk] - mn1);
      Ps[qi][g * 8 + kk] = p0;
      Ps[qi + 32][g * 8 + kk] = p1;
      l0 += p0; l1 += p1;
    }
#pragma unroll
    for (int o = 1; o < 8; o <<= 1) {
      l0 += __shfl_xor_sync(0xffffffffu, l0, o);
      l1 += __shfl_xor_sync(0xffffffffu, l1, o);
    }
    Z0 = Z0 * f0 + l0; Z1 = Z1 * f1 + l1;
    m0 = mn0; m1 = mn1;
    a00 *= f0; a01 *= f0; a02 *= f0; a03 *= f0;
    a10 *= f1; a11 *= f1; a12 *= f1; a13 *= f1;
    __syncwarp();

    int d0i = g * 4;
#pragma unroll 8
    for (int key = 0; key < 64; key++) {
      float4 v = *(const float4*)&Vs[key][d0i];
      float p0 = Ps[qi][key];
      float p1 = Ps[qi + 32][key];
      a00 += p0 * v.x; a01 += p0 * v.y; a02 += p0 * v.z; a03 += p0 * v.w;
      a10 += p1 * v.x; a11 += p1 * v.y; a12 += p1 * v.z; a13 += p1 * v.w;
    }
    __syncthreads();
  }
  float i0 = 1.f / Z0, i1 = 1.f / Z1;
  float4 o0 = {a00 * i0, a01 * i0, a02 * i0, a03 * i0};
  float4 o1 = {a10 * i1, a11 * i1, a12 * i1, a13 * i1};
  *(float4*)(g_ctx + (size_t)(qb + qi) * 256 + h * 32 + g * 4) = o0;
  *(float4*)(g_ctx + (size_t)(qb + qi + 32) * 256 + h * 32 + g * 4) = o1;
}

// ---------------- residual + LayerNorm: out = LN(a+b)*g+beta ----------------
__global__ __launch_bounds__(256) void ln_res(const float* __restrict__ a,
                                              const float* __restrict__ b,
                                              const float* __restrict__ gam,
                                              const float* __restrict__ bet,
                                              float* __restrict__ out) {
  int w = threadIdx.x >> 5, lane = threadIdx.x & 31;
  int row = blockIdx.x * 8 + w;
  float x[8];
  float s = 0.f;
#pragma unroll
  for (int i = 0; i < 8; i++) {
    int d = lane + i * 32;
    x[i] = a[(size_t)row * 256 + d] + b[(size_t)row * 256 + d];
    s += x[i];
  }
#pragma unroll
  for (int o = 16; o; o >>= 1) s += __shfl_xor_sync(0xffffffffu, s, o);
  float mean = s * (1.f / 256.f);
  float v = 0.f;
#pragma unroll
  for (int i = 0; i < 8; i++) {
    float t = x[i] - mean;
    v += t * t;
  }
#pragma unroll
  for (int o = 16; o; o >>= 1) v += __shfl_xor_sync(0xffffffffu, v, o);
  float r = rsqrtf(v * (1.f / 256.f) + 1e-5f);
#pragma unroll
  for (int i = 0; i < 8; i++) {
    int d = lane + i * 32;
    out[(size_t)row * 256 + d] = (x[i] - mean) * r * gam[d] + bet[d];
  }
}

// ---------------- GAT attention dot products ----------------
__global__ __launch_bounds__(256) void gat_dots(const float* __restrict__ att_src,
                                                const float* __restrict__ att_dst) {
  int n = blockIdx.x;
  int w = threadIdx.x >> 5, lane = threadIdx.x & 31;
  const float* row = g_hw + (size_t)n * 2048 + w * 256;
  float s1 = 0.f, s2 = 0.f;
#pragma unroll
  for (int i = 0; i < 8; i++) {
    int d = lane + i * 32;
    float v = row[d];
    s1 += v * att_src[w * 256 + d];
    s2 += v * att_dst[w * 256 + d];
  }
#pragma unroll
  for (int o = 16; o; o >>= 1) {
    s1 += __shfl_xor_sync(0xffffffffu, s1, o);
    s2 += __shfl_xor_sync(0xffffffffu, s2, o);
  }
  if (!lane) {
    g_asrc[n * 8 + w] = s1;
    g_adst[n * 8 + w] = s2;
  }
}

// ---------------- CSR build ----------------
__global__ void csr_zero() {
  int i = blockIdx.x * 256 + threadIdx.x;
  if (i < N_NODES) g_deg[i] = 0;
}
__global__ void csr_count(const int* __restrict__ ei) {
  int i = blockIdx.x * 256 + threadIdx.x;
  if (i >= EN_EDGES) return;
  int d = (i < E_EDGES) ? ei[E_EDGES + i] : (i - E_EDGES);
  atomicAdd(&g_deg[d], 1);
}
__global__ __launch_bounds__(1024) void csr_scan() {
  __shared__ int s[1024];
  int tid = threadIdx.x;
  int v0 = g_deg[tid * 4 + 0], v1 = g_deg[tid * 4 + 1];
  int v2 = g_deg[tid * 4 + 2], v3 = g_deg[tid * 4 + 3];
  int tsum = v0 + v1 + v2 + v3;
  s[tid] = tsum;
  __syncthreads();
  for (int o = 1; o < 1024; o <<= 1) {
    int t = (tid >= o) ? s[tid - o] : 0;
    __syncthreads();
    s[tid] += t;
    __syncthreads();
  }
  int excl = tid ? s[tid - 1] : 0;
  int o0 = excl, o1 = o0 + v0, o2 = o1 + v1, o3 = o2 + v2;
  g_off[tid * 4 + 0] = o0; g_cursor[tid * 4 + 0] = o0;
  g_off[tid * 4 + 1] = o1; g_cursor[tid * 4 + 1] = o1;
  g_off[tid * 4 + 2] = o2; g_cursor[tid * 4 + 2] = o2;
  g_off[tid * 4 + 3] = o3; g_cursor[tid * 4 + 3] = o3;
  if (tid == 1023) g_off[N_NODES] = excl + tsum;
}
__global__ void csr_fill(const int* __restrict__ ei) {
  int i = blockIdx.x * 256 + threadIdx.x;
  if (i >= EN_EDGES) return;
  int srcv = (i < E_EDGES) ? ei[i] : (i - E_EDGES);
  int dstv = (i < E_EDGES) ? ei[E_EDGES + i] : (i - E_EDGES);
  int pos = atomicAdd(&g_cursor[dstv], 1);
  g_csrc[pos] = srcv;
}

// ---------------- GAT aggregation: one block per destination node ----------
__global__ __launch_bounds__(256) void gat_agg(const float* __restrict__ gat_bias) {
  int n = blockIdx.x, tid = threadIdx.x;
  __shared__ int ssrc[256];
  __shared__ float se[256 * 8];
  __shared__ float sm[8], sz[8], sfac[8], sadst[8];
  __shared__ float sred[8 * 32];

  int start = g_off[n], end = g_off[n + 1];
  if (tid < 8) {
    sm[tid] = -1e30f;
    sz[tid] = 0.f;
    sadst[tid] = g_adst[n * 8 + tid];
  }
  float acc[8];
#pragma unroll
  for (int i = 0; i < 8; i++) acc[i] = 0.f;
  __syncthreads();

  for (int cs = start; cs < end; cs += 256) {
    int cnt = min(256, end - cs);
    if (tid < cnt) ssrc[tid] = g_csrc[cs + tid];
    __syncthreads();
#pragma unroll
    for (int j = 0; j < 8; j++) {
      int idx = tid + j * 256;
      int eidx = idx >> 3, hh = idx & 7;
      if (eidx < cnt) {
        float v = g_asrc[ssrc[eidx] * 8 + hh] + sadst[hh];
        se[idx] = (v > 0.f) ? v : 0.2f * v;
      }
    }
    __syncthreads();
    int h = tid & 7, gg = tid >> 3;
    float mx = -1e30f;
    for (int e = gg; e < cnt; e += 32) mx = fmaxf(mx, se[e * 8 + h]);
    sred[h * 32 + gg] = mx;
    __syncthreads();
    if (tid < 8) {
      float m2 = -1e30f;
      for (int g2 = 0; g2 < 32; g2++) m2 = fmaxf(m2, sred[tid * 32 + g2]);
      float mold = sm[tid];
      float mnew = fmaxf(mold, m2);
      sfac[tid] = __expf(mold - mnew);
      sm[tid] = mnew;
      sz[tid] *= sfac[tid];
    }
    __syncthreads();
#pragma unroll
    for (int i = 0; i < 8; i++) acc[i] *= sfac[i];
    float sum = 0.f;
    for (int e = gg; e < cnt; e += 32) {
      float p = __expf(se[e * 8 + h] - sm[h]);
      se[e * 8 + h] = p;
      sum += p;
    }
    sred[h * 32 + gg] = sum;
    __syncthreads();
    if (tid < 8) {
      float s2 = 0.f;
      for (int g2 = 0; g2 < 32; g2++) s2 += sred[tid * 32 + g2];
      sz[tid] += s2;
    }
    __syncthreads();
    for (int e = 0; e < cnt; e++) {
      const float* row = g_hw + (size_t)ssrc[e] * 2048;
#pragma unroll
      for (int hh = 0; hh < 8; hh++)
        acc[hh] += se[e * 8 + hh] * row[hh * 256 + tid];
    }
    __syncthreads();
  }
  float r = 0.f;
#pragma unroll
  for (int hh = 0; hh < 8; hh++) r += acc[hh] / (sz[hh] + 1e-16f);
  g_hg[(size_t)n * 256 + tid] = r * 0.125f + gat_bias[tid];
}

// ---------------- fused classifier: gather + GEMM1 + relu + GEMM2 + sigmoid
__global__ __launch_bounds__(256) void classify(
    const float* __restrict__ w1, const float* __restrict__ b1,
    const float* __restrict__ w2, const float* __restrict__ b2,
    const int* __restrict__ iA, const int* __restrict__ iB,
    float* __restrict__ out) {
  __shared__ float sp[16][512];
  __shared__ int sia[16], sib[16];
  int tid = threadIdx.x;
  int bp = blockIdx.x * 16;
  if (tid < 16) sia[tid] = iA[bp + tid];
  else if (tid < 32) sib[tid - 16] = iB[bp + tid - 16];
  __syncthreads();
#pragma unroll
  for (int j = 0; j < 8; j++) {
    int idx4 = tid + j * 256;
    int p = idx4 >> 7;
    int c = (idx4 & 127) * 4;
    const float* src = (c < 256) ? (g_hg + (size_t)sia[p] * 256 + c)
                                 : (g_hg + (size_t)sib[p] * 256 + (c - 256));
    *(float4*)&sp[p][c] = *(const float4*)src;
  }
  __syncthreads();
  int p = tid >> 4;
  int j0 = (tid & 15) * 4;
  float a0 = 0.f, a1 = 0.f, a2 = 0.f, a3 = 0.f;
  for (int k = 0; k < 512; k++) {
    float s = sp[p][k];
    float4 w = *(const float4*)(w1 + (size_t)k * 64 + j0);
    a0 += s * w.x; a1 += s * w.y; a2 += s * w.z; a3 += s * w.w;
  }
  a0 = fmaxf(a0 + b1[j0 + 0], 0.f);
  a1 = fmaxf(a1 + b1[j0 + 1], 0.f);
  a2 = fmaxf(a2 + b1[j0 + 2], 0.f);
  a3 = fmaxf(a3 + b1[j0 + 3], 0.f);
  float part = a0 * w2[j0 + 0] + a1 * w2[j0 + 1] + a2 * w2[j0 + 2] + a3 * w2[j0 + 3];
#pragma unroll
  for (int o = 1; o < 16; o <<= 1) part += __shfl_xor_sync(0xffffffffu, part, o);
  if ((tid & 15) == 0) {
    float z = part + b2[0];
    out[bp + p] = 1.f / (1.f + __expf(-z));
  }
}

// ---------------- launch ----------------
extern "C" void kernel_launch(void* const* d_in, const int* in_sizes, int n_in,
                              void* d_out, int out_size) {
  const float* x = (const float*)d_in[0];
  const int* edge_index = (const int*)d_in[1];
  const int* idx_A = (const int*)d_in[2];
  const int* idx_B = (const int*)d_in[3];
  const float* w_in = (const float*)d_in[4];
  const float* b_in = (const float*)d_in[5];
  const float* w_qkv = (const float*)d_in[6];
  const float* b_qkv = (const float*)d_in[7];
  const float* w_o = (const float*)d_in[8];
  const float* b_o = (const float*)d_in[9];
  const float* ln1_g = (const float*)d_in[10];
  const float* ln1_b = (const float*)d_in[11];
  const float* w_ff1 = (const float*)d_in[12];
  const float* b_ff1 = (const float*)d_in[13];
  const float* w_ff2 = (const float*)d_in[14];
  const float* b_ff2 = (const float*)d_in[15];
  const float* ln2_g = (const float*)d_in[16];
  const float* ln2_b = (const float*)d_in[17];
  const float* gat_w = (const float*)d_in[18];
  const float* att_src = (const float*)d_in[19];
  const float* att_dst = (const float*)d_in[20];
  const float* gat_bias = (const float*)d_in[21];
  const float* cls_w1 = (const float*)d_in[22];
  const float* cls_b1 = (const float*)d_in[23];
  const float* cls_w2 = (const float*)d_in[24];
  const float* cls_b2 = (const float*)d_in[25];
  float* out = (float*)d_out;

  void* p;
  cudaGetSymbolAddress(&p, g_h);   float* ph = (float*)p;
  cudaGetSymbolAddress(&p, g_qkv); float* pqkv = (float*)p;
  cudaGetSymbolAddress(&p, g_ctx); float* pctx = (float*)p;
  cudaGetSymbolAddress(&p, g_tmp); float* ptmp = (float*)p;
  cudaGetSymbolAddress(&p, g_h1);  float* ph1 = (float*)p;
  cudaGetSymbolAddress(&p, g_ff);  float* pff = (float*)p;
  cudaGetSymbolAddress(&p, g_h2);  float* ph2 = (float*)p;
  cudaGetSymbolAddress(&p, g_hw);  float* phw = (float*)p;

  // 1. input projection: h = x @ w_in + b_in
  mma_gemm<0><<<dim3(D_MODEL / 64, N_NODES / 128), 256>>>(
      x, w_in, b_in, ph, N_NODES, D_MODEL, D_INP);
  // 2. qkv
  mma_gemm<0><<<dim3(3 * D_MODEL / 64, N_NODES / 128), 256>>>(
      ph, w_qkv, b_qkv, pqkv, N_NODES, 3 * D_MODEL, D_MODEL);
  // 3. attention
  attn_kernel<<<dim3(N_NODES / 64, H_HEADS), 256>>>();
  // 4. ctx @ w_o + b_o
  mma_gemm<0><<<dim3(D_MODEL / 64, N_NODES / 128), 256>>>(
      pctx, w_o, b_o, ptmp, N_NODES, D_MODEL, D_MODEL);
  // 5. LN1(h + attn_out)
  ln_res<<<N_NODES / 8, 256>>>(ph, ptmp, ln1_g, ln1_b, ph1);
  // 6. ff1 + relu
  mma_gemm<1><<<dim3(FF_DIM / 64, N_NODES / 128), 256>>>(
      ph1, w_ff1, b_ff1, pff, N_NODES, FF_DIM, D_MODEL);
  // 7. ff2
  mma_gemm<0><<<dim3(D_MODEL / 64, N_NODES / 128), 256>>>(
      pff, w_ff2, b_ff2, ptmp, N_NODES, D_MODEL, FF_DIM);
  // 8. LN2(h1 + ff)
  ln_res<<<N_NODES / 8, 256>>>(ph1, ptmp, ln2_g, ln2_b, ph2);
  // 9. GAT projection: hw = h2 @ gat_w
  mma_gemm<0><<<dim3(H_HEADS * D_MODEL / 64, N_NODES / 128), 256>>>(
      ph2, gat_w, (const float*)nullptr, phw, N_NODES, H_HEADS * D_MODEL,
      D_MODEL);
  // 10. per-node attention logits
  gat_dots<<<N_NODES, 256>>>(att_src, att_dst);
  // 11. CSR by destination
  csr_zero<<<(N_NODES + 255) / 256, 256>>>();
  csr_count<<<(EN_EDGES + 255) / 256, 256>>>(edge_index);
  csr_scan<<<1, 1024>>>();
  csr_fill<<<(EN_EDGES + 255) / 256, 256>>>(edge_index);
  // 12. scatter-softmax aggregation -> hg
  gat_agg<<<N_NODES, 256>>>(gat_bias);
  // 13. fused pairwise classifier -> out
  classify<<<B_PAIRS / 16, 256>>>(cls_w1, cls_b1, cls_w2, cls_b2, idx_A, idx_B,
                                  out);
}

// round 3
// speedup vs baseline: 7.3631x; 4.4828x over previous
#include <cuda_runtime.h>
#include <math.h>
#include <stdint.h>

#define N_NODES 4096
#define E_EDGES 131072
#define EN_EDGES (E_EDGES + N_NODES)
#define D_INP 128
#define D_MODEL 256
#define H_HEADS 8
#define D_HEAD 32
#define FF_DIM 2048
#define B_PAIRS 16384

// ---------------- scratch (device globals; allocation-free) ----------------
__device__ __align__(256) float g_h[N_NODES * D_MODEL];
__device__ __align__(256) float g_qkv[N_NODES * 3 * D_MODEL];
__device__ __align__(256) float g_ctx[N_NODES * D_MODEL];
__device__ __align__(256) float g_tmp[N_NODES * D_MODEL];
__device__ __align__(256) float g_h1[N_NODES * D_MODEL];
__device__ __align__(256) float g_ff[N_NODES * FF_DIM];
__device__ __align__(256) float g_h2[N_NODES * D_MODEL];
__device__ __align__(256) float g_hw[N_NODES * H_HEADS * D_MODEL];
__device__ __align__(256) float g_asrc[N_NODES * H_HEADS];
__device__ __align__(256) float g_adst[N_NODES * H_HEADS];
__device__ __align__(256) float g_hg[N_NODES * D_MODEL];
__device__ int g_deg[N_NODES];
__device__ int g_off[N_NODES + 1];
__device__ int g_cursor[N_NODES];
__device__ int g_csrc[EN_EDGES];

// ---------------- TF32 helpers ----------------
__device__ __forceinline__ uint32_t f2tf32(float x) {
  uint32_t r;
  asm("cvt.rna.tf32.f32 %0, %1;" : "=r"(r) : "f"(x));
  return r;
}
__device__ __forceinline__ float tf32f(float x) {
  return __uint_as_float(f2tf32(x));
}
__device__ __forceinline__ void mma_tf32(float* d, const uint32_t* a,
                                         const uint32_t* b) {
  asm volatile(
      "mma.sync.aligned.m16n8k8.row.col.f32.tf32.tf32.f32 "
      "{%0,%1,%2,%3}, {%4,%5,%6,%7}, {%8,%9}, {%0,%1,%2,%3};\n"
      : "+f"(d[0]), "+f"(d[1]), "+f"(d[2]), "+f"(d[3])
      : "r"(a[0]), "r"(a[1]), "r"(a[2]), "r"(a[3]), "r"(b[0]), "r"(b[1]));
}

// ---------------- TF32 tensor-core GEMM: C[M,N] = A[M,K] @ B[K,N] ----------
// Tile 128x64x16, 256 threads (8 warps: 4 along M x 2 along N), warp tile
// 32x32. Software-pipelined global loads.
template <int RELU>
__global__ __launch_bounds__(256) void mma_gemm(
    const float* __restrict__ A, const float* __restrict__ B,
    const float* __restrict__ bias, float* __restrict__ C,
    int M, int Nn, int K) {
  __shared__ float As[128][20];
  __shared__ float Bs[16][72];
  int tid = threadIdx.x;
  int warp = tid >> 5, lane = tid & 31;
  int gid = lane >> 2, tig = lane & 3;
  int bm = blockIdx.y * 128, bn = blockIdx.x * 64;
  int wm = (warp & 3) * 32;
  int wn = (warp >> 2) * 32;

  float acc[2][4][4];
#pragma unroll
  for (int t = 0; t < 2; t++)
#pragma unroll
    for (int u = 0; u < 4; u++)
#pragma unroll
      for (int i = 0; i < 4; i++) acc[t][u][i] = 0.f;

  int ar = tid >> 1, ac = (tid & 1) * 8;
  int br = tid >> 4, bc = (tid & 15) * 4;

  // preload first tile
  float4 av0 = *(const float4*)(A + (size_t)(bm + ar) * K + ac);
  float4 av1 = *(const float4*)(A + (size_t)(bm + ar) * K + ac + 4);
  float4 bv = *(const float4*)(B + (size_t)br * Nn + bn + bc);

  for (int k0 = 0; k0 < K; k0 += 16) {
    As[ar][ac + 0] = tf32f(av0.x); As[ar][ac + 1] = tf32f(av0.y);
    As[ar][ac + 2] = tf32f(av0.z); As[ar][ac + 3] = tf32f(av0.w);
    As[ar][ac + 4] = tf32f(av1.x); As[ar][ac + 5] = tf32f(av1.y);
    As[ar][ac + 6] = tf32f(av1.z); As[ar][ac + 7] = tf32f(av1.w);
    Bs[br][bc + 0] = tf32f(bv.x); Bs[br][bc + 1] = tf32f(bv.y);
    Bs[br][bc + 2] = tf32f(bv.z); Bs[br][bc + 3] = tf32f(bv.w);
    __syncthreads();
    if (k0 + 16 < K) {  // prefetch next tile; overlaps compute below
      av0 = *(const float4*)(A + (size_t)(bm + ar) * K + k0 + 16 + ac);
      av1 = *(const float4*)(A + (size_t)(bm + ar) * K + k0 + 16 + ac + 4);
      bv = *(const float4*)(B + (size_t)(k0 + 16 + br) * Nn + bn + bc);
    }
#pragma unroll
    for (int ks = 0; ks < 16; ks += 8) {
      uint32_t af[2][4], bf[4][2];
#pragma unroll
      for (int t = 0; t < 2; t++) {
        int row = wm + t * 16 + gid;
        af[t][0] = __float_as_uint(As[row][ks + tig]);
        af[t][1] = __float_as_uint(As[row + 8][ks + tig]);
        af[t][2] = __float_as_uint(As[row][ks + tig + 4]);
        af[t][3] = __float_as_uint(As[row + 8][ks + tig + 4]);
      }
#pragma unroll
      for (int u = 0; u < 4; u++) {
        int col = wn + u * 8 + gid;
        bf[u][0] = __float_as_uint(Bs[ks + tig][col]);
        bf[u][1] = __float_as_uint(Bs[ks + tig + 4][col]);
      }
#pragma unroll
      for (int t = 0; t < 2; t++)
#pragma unroll
        for (int u = 0; u < 4; u++) mma_tf32(acc[t][u], af[t], bf[u]);
    }
    __syncthreads();
  }

#pragma unroll
  for (int t = 0; t < 2; t++) {
#pragma unroll
    for (int u = 0; u < 4; u++) {
      int r = bm + wm + t * 16 + gid;
      int c = bn + wn + u * 8 + tig * 2;
      float b0 = bias ? bias[c] : 0.f;
      float b1 = bias ? bias[c + 1] : 0.f;
      float2 o0 = {acc[t][u][0] + b0, acc[t][u][1] + b1};
      float2 o1 = {acc[t][u][2] + b0, acc[t][u][3] + b1};
      if (RELU) {
        o0.x = fmaxf(o0.x, 0.f); o0.y = fmaxf(o0.y, 0.f);
        o1.x = fmaxf(o1.x, 0.f); o1.y = fmaxf(o1.y, 0.f);
      }
      *(float2*)(C + (size_t)r * Nn + c) = o0;
      *(float2*)(C + (size_t)(r + 8) * Nn + c) = o1;
    }
  }
}

// ---------------- TF32 tensor-core flash attention ----------------
// grid (N/64, H), block 128 (4 warps x 16 q-rows). Tiles: 64q x 64k, DH=32.
// All smem strides chosen conflict-free for fragment access patterns:
//  Ks stride 36 (=4 mod 32), Vs stride 40 (=8 mod 32), Ps stride 68 (=4 mod 32)
__global__ __launch_bounds__(128) void attn_mma() {
  __shared__ float Ks[64][36];
  __shared__ float Vs[64][40];
  __shared__ float Ps[64][68];
  int tid = threadIdx.x;
  int warp = tid >> 5, lane = tid & 31;
  int gid = lane >> 2, tig = lane & 3;
  int h = blockIdx.y;
  int qb = blockIdx.x * 64;
  int r0 = warp * 16 + gid;
  const float scale = 0.17677669529663687f;  // 1/sqrt(32)

  // ---- stage Q tile (64x32) through Ks, build scaled tf32 A-fragments
#pragma unroll
  for (int j = 0; j < 4; j++) {
    int idx = tid + j * 128;
    int r = idx >> 3, c4 = (idx & 7) * 4;
    float4 v = *(const float4*)(g_qkv + (size_t)(qb + r) * 768 + h * 32 + c4);
    Ks[r][c4 + 0] = tf32f(v.x * scale);
    Ks[r][c4 + 1] = tf32f(v.y * scale);
    Ks[r][c4 + 2] = tf32f(v.z * scale);
    Ks[r][c4 + 3] = tf32f(v.w * scale);
  }
  __syncthreads();
  uint32_t qf[4][4];
#pragma unroll
  for (int ks = 0; ks < 4; ks++) {
    qf[ks][0] = __float_as_uint(Ks[r0][ks * 8 + tig]);
    qf[ks][1] = __float_as_uint(Ks[r0 + 8][ks * 8 + tig]);
    qf[ks][2] = __float_as_uint(Ks[r0][ks * 8 + tig + 4]);
    qf[ks][3] = __float_as_uint(Ks[r0 + 8][ks * 8 + tig + 4]);
  }
  __syncthreads();

  float m0 = -1e30f, m1 = -1e30f, Z0 = 0.f, Z1 = 0.f;
  float oacc[4][4];
#pragma unroll
  for (int u = 0; u < 4; u++)
#pragma unroll
    for (int i = 0; i < 4; i++) oacc[u][i] = 0.f;

  for (int kt = 0; kt < N_NODES; kt += 64) {
    // ---- load K,V tiles (64x32 each)
#pragma unroll
    for (int j = 0; j < 4; j++) {
      int idx = tid + j * 128;
      int r = idx >> 3, c4 = (idx & 7) * 4;
      const float* base = g_qkv + (size_t)(kt + r) * 768 + h * 32 + c4;
      float4 kv = *(const float4*)(base + 256);
      float4 vv = *(const float4*)(base + 512);
      Ks[r][c4 + 0] = tf32f(kv.x); Ks[r][c4 + 1] = tf32f(kv.y);
      Ks[r][c4 + 2] = tf32f(kv.z); Ks[r][c4 + 3] = tf32f(kv.w);
      Vs[r][c4 + 0] = tf32f(vv.x); Vs[r][c4 + 1] = tf32f(vv.y);
      Vs[r][c4 + 2] = tf32f(vv.z); Vs[r][c4 + 3] = tf32f(vv.w);
    }
    __syncthreads();

    // ---- S = Q @ K^T (scaled): 8 n-tiles of 8 keys
    float s[8][4];
#pragma unroll
    for (int u = 0; u < 8; u++) {
      s[u][0] = s[u][1] = s[u][2] = s[u][3] = 0.f;
#pragma unroll
      for (int ks = 0; ks < 4; ks++) {
        uint32_t bf[2];
        bf[0] = __float_as_uint(Ks[u * 8 + gid][ks * 8 + tig]);
        bf[1] = __float_as_uint(Ks[u * 8 + gid][ks * 8 + tig + 4]);
        mma_tf32(s[u], qf[ks], bf);
      }
    }
    // ---- row max (rows r0, r0+8)
    float t0 = -1e30f, t1 = -1e30f;
#pragma unroll
    for (int u = 0; u < 8; u++) {
      t0 = fmaxf(t0, fmaxf(s[u][0], s[u][1]));
      t1 = fmaxf(t1, fmaxf(s[u][2], s[u][3]));
    }
#pragma unroll
    for (int o = 1; o < 4; o <<= 1) {
      t0 = fmaxf(t0, __shfl_xor_sync(0xffffffffu, t0, o));
      t1 = fmaxf(t1, __shfl_xor_sync(0xffffffffu, t1, o));
    }
    float mn0 = fmaxf(m0, t0), mn1 = fmaxf(m1, t1);
    float f0 = __expf(m0 - mn0), f1 = __expf(m1 - mn1);
    m0 = mn0; m1 = mn1;
    // ---- P = exp(S - m), store to Ps (tf32), accumulate row sums
    float l0 = 0.f, l1 = 0.f;
#pragma unroll
    for (int u = 0; u < 8; u++) {
      float p00 = __expf(s[u][0] - mn0);
      float p01 = __expf(s[u][1] - mn0);
      float p10 = __expf(s[u][2] - mn1);
      float p11 = __expf(s[u][3] - mn1);
      l0 += p00 + p01; l1 += p10 + p11;
      float2 w0 = {tf32f(p00), tf32f(p01)};
      float2 w1 = {tf32f(p10), tf32f(p11)};
      *(float2*)&Ps[r0][u * 8 + tig * 2] = w0;
      *(float2*)&Ps[r0 + 8][u * 8 + tig * 2] = w1;
    }
#pragma unroll
    for (int o = 1; o < 4; o <<= 1) {
      l0 += __shfl_xor_sync(0xffffffffu, l0, o);
      l1 += __shfl_xor_sync(0xffffffffu, l1, o);
    }
    Z0 = Z0 * f0 + l0;
    Z1 = Z1 * f1 + l1;
#pragma unroll
    for (int u = 0; u < 4; u++) {
      oacc[u][0] *= f0; oacc[u][1] *= f0;
      oacc[u][2] *= f1; oacc[u][3] *= f1;
    }
    __syncwarp();  // Ps rows are private to this warp

    // ---- O += P @ V : 8 k-steps, 4 d-tiles
#pragma unroll
    for (int ks = 0; ks < 8; ks++) {
      uint32_t af[4];
      af[0] = __float_as_uint(Ps[r0][ks * 8 + tig]);
      af[1] = __float_as_uint(Ps[r0 + 8][ks * 8 + tig]);
      af[2] = __float_as_uint(Ps[r0][ks * 8 + tig + 4]);
      af[3] = __float_as_uint(Ps[r0 + 8][ks * 8 + tig + 4]);
#pragma unroll
      for (int u = 0; u < 4; u++) {
        uint32_t bf[2];
        bf[0] = __float_as_uint(Vs[ks * 8 + tig][u * 8 + gid]);
        bf[1] = __float_as_uint(Vs[ks * 8 + tig + 4][u * 8 + gid]);
        mma_tf32(oacc[u], af, bf);
      }
    }
    __syncthreads();
  }

  float i0 = 1.f / Z0, i1 = 1.f / Z1;
#pragma unroll
  for (int u = 0; u < 4; u++) {
    float2 o0 = {oacc[u][0] * i0, oacc[u][1] * i0};
    float2 o1 = {oacc[u][2] * i1, oacc[u][3] * i1};
    int c = h * 32 + u * 8 + tig * 2;
    *(float2*)(g_ctx + (size_t)(qb + r0) * 256 + c) = o0;
    *(float2*)(g_ctx + (size_t)(qb + r0 + 8) * 256 + c) = o1;
  }
}

// ---------------- residual + LayerNorm ----------------
__global__ __launch_bounds__(256) void ln_res(const float* __restrict__ a,
                                              const float* __restrict__ b,
                                              const float* __restrict__ gam,
                                              const float* __restrict__ bet,
                                              float* __restrict__ out) {
  int w = threadIdx.x >> 5, lane = threadIdx.x & 31;
  int row = blockIdx.x * 8 + w;
  float x[8];
  float s = 0.f;
#pragma unroll
  for (int i = 0; i < 8; i++) {
    int d = lane + i * 32;
    x[i] = a[(size_t)row * 256 + d] + b[(size_t)row * 256 + d];
    s += x[i];
  }
#pragma unroll
  for (int o = 16; o; o >>= 1) s += __shfl_xor_sync(0xffffffffu, s, o);
  float mean = s * (1.f / 256.f);
  float v = 0.f;
#pragma unroll
  for (int i = 0; i < 8; i++) {
    float t = x[i] - mean;
    v += t * t;
  }
#pragma unroll
  for (int o = 16; o; o >>= 1) v += __shfl_xor_sync(0xffffffffu, v, o);
  float r = rsqrtf(v * (1.f / 256.f) + 1e-5f);
#pragma unroll
  for (int i = 0; i < 8; i++) {
    int d = lane + i * 32;
    out[(size_t)row * 256 + d] = (x[i] - mean) * r * gam[d] + bet[d];
  }
}

// ---------------- GAT attention dot products ----------------
__global__ __launch_bounds__(256) void gat_dots(const float* __restrict__ att_src,
                                                const float* __restrict__ att_dst) {
  int n = blockIdx.x;
  int w = threadIdx.x >> 5, lane = threadIdx.x & 31;
  const float* row = g_hw + (size_t)n * 2048 + w * 256;
  float s1 = 0.f, s2 = 0.f;
#pragma unroll
  for (int i = 0; i < 8; i++) {
    int d = lane + i * 32;
    float v = row[d];
    s1 += v * att_src[w * 256 + d];
    s2 += v * att_dst[w * 256 + d];
  }
#pragma unroll
  for (int o = 16; o; o >>= 1) {
    s1 += __shfl_xor_sync(0xffffffffu, s1, o);
    s2 += __shfl_xor_sync(0xffffffffu, s2, o);
  }
  if (!lane) {
    g_asrc[n * 8 + w] = s1;
    g_adst[n * 8 + w] = s2;
  }
}

// ---------------- CSR build ----------------
__global__ void csr_zero() {
  int i = blockIdx.x * 256 + threadIdx.x;
  if (i < N_NODES) g_deg[i] = 0;
}
__global__ void csr_count(const int* __restrict__ ei) {
  int i = blockIdx.x * 256 + threadIdx.x;
  if (i >= EN_EDGES) return;
  int d = (i < E_EDGES) ? ei[E_EDGES + i] : (i - E_EDGES);
  atomicAdd(&g_deg[d], 1);
}
__global__ __launch_bounds__(1024) void csr_scan() {
  __shared__ int s[1024];
  int tid = threadIdx.x;
  int v0 = g_deg[tid * 4 + 0], v1 = g_deg[tid * 4 + 1];
  int v2 = g_deg[tid * 4 + 2], v3 = g_deg[tid * 4 + 3];
  int tsum = v0 + v1 + v2 + v3;
  s[tid] = tsum;
  __syncthreads();
  for (int o = 1; o < 1024; o <<= 1) {
    int t = (tid >= o) ? s[tid - o] : 0;
    __syncthreads();
    s[tid] += t;
    __syncthreads();
  }
  int excl = tid ? s[tid - 1] : 0;
  int o0 = excl, o1 = o0 + v0, o2 = o1 + v1, o3 = o2 + v2;
  g_off[tid * 4 + 0] = o0; g_cursor[tid * 4 + 0] = o0;
  g_off[tid * 4 + 1] = o1; g_cursor[tid * 4 + 1] = o1;
  g_off[tid * 4 + 2] = o2; g_cursor[tid * 4 + 2] = o2;
  g_off[tid * 4 + 3] = o3; g_cursor[tid * 4 + 3] = o3;
  if (tid == 1023) g_off[N_NODES] = excl + tsum;
}
__global__ void csr_fill(const int* __restrict__ ei) {
  int i = blockIdx.x * 256 + threadIdx.x;
  if (i >= EN_EDGES) return;
  int srcv = (i < E_EDGES) ? ei[i] : (i - E_EDGES);
  int dstv = (i < E_EDGES) ? ei[E_EDGES + i] : (i - E_EDGES);
  int pos = atomicAdd(&g_cursor[dstv], 1);
  g_csrc[pos] = srcv;
}

// ---------------- GAT aggregation ----------------
__global__ __launch_bounds__(256) void gat_agg(const float* __restrict__ gat_bias) {
  int n = blockIdx.x, tid = threadIdx.x;
  __shared__ int ssrc[256];
  __shared__ float se[256 * 8];
  __shared__ float sm[8], sz[8], sfac[8], sadst[8];
  __shared__ float sred[8 * 32];

  int start = g_off[n], end = g_off[n + 1];
  if (tid < 8) {
    sm[tid] = -1e30f;
    sz[tid] = 0.f;
    sadst[tid] = g_adst[n * 8 + tid];
  }
  float acc[8];
#pragma unroll
  for (int i = 0; i < 8; i++) acc[i] = 0.f;
  __syncthreads();

  for (int cs = start; cs < end; cs += 256) {
    int cnt = min(256, end - cs);
    if (tid < cnt) ssrc[tid] = g_csrc[cs + tid];
    __syncthreads();
#pragma unroll
    for (int j = 0; j < 8; j++) {
      int idx = tid + j * 256;
      int eidx = idx >> 3, hh = idx & 7;
      if (eidx < cnt) {
        float v = g_asrc[ssrc[eidx] * 8 + hh] + sadst[hh];
        se[idx] = (v > 0.f) ? v : 0.2f * v;
      }
    }
    __syncthreads();
    int h = tid & 7, gg = tid >> 3;
    float mx = -1e30f;
    for (int e = gg; e < cnt; e += 32) mx = fmaxf(mx, se[e * 8 + h]);
    sred[h * 32 + gg] = mx;
    __syncthreads();
    if (tid < 8) {
      float m2 = -1e30f;
      for (int g2 = 0; g2 < 32; g2++) m2 = fmaxf(m2, sred[tid * 32 + g2]);
      float mold = sm[tid];
      float mnew = fmaxf(mold, m2);
      sfac[tid] = __expf(mold - mnew);
      sm[tid] = mnew;
      sz[tid] *= sfac[tid];
    }
    __syncthreads();
#pragma unroll
    for (int i = 0; i < 8; i++) acc[i] *= sfac[i];
    float sum = 0.f;
    for (int e = gg; e < cnt; e += 32) {
      float p = __expf(se[e * 8 + h] - sm[h]);
      se[e * 8 + h] = p;
      sum += p;
    }
    sred[h * 32 + gg] = sum;
    __syncthreads();
    if (tid < 8) {
      float s2 = 0.f;
      for (int g2 = 0; g2 < 32; g2++) s2 += sred[tid * 32 + g2];
      sz[tid] += s2;
    }
    __syncthreads();
    for (int e = 0; e < cnt; e++) {
      const float* row = g_hw + (size_t)ssrc[e] * 2048;
#pragma unroll
      for (int hh = 0; hh < 8; hh++)
        acc[hh] += se[e * 8 + hh] * row[hh * 256 + tid];
    }
    __syncthreads();
  }
  float r = 0.f;
#pragma unroll
  for (int hh = 0; hh < 8; hh++) r += acc[hh] / (sz[hh] + 1e-16f);
  g_hg[(size_t)n * 256 + tid] = r * 0.125f + gat_bias[tid];
}

// ---------------- fused classifier ----------------
__global__ __launch_bounds__(256) void classify(
    const float* __restrict__ w1, const float* __restrict__ b1,
    const float* __restrict__ w2, const float* __restrict__ b2,
    const int* __restrict__ iA, const int* __restrict__ iB,
    float* __restrict__ out) {
  __shared__ float sp[16][512];
  __shared__ int sia[16], sib[16];
  int tid = threadIdx.x;
  int bp = blockIdx.x * 16;
  if (tid < 16) sia[tid] = iA[bp + tid];
  else if (tid < 32) sib[tid - 16] = iB[bp + tid - 16];
  __syncthreads();
#pragma unroll
  for (int j = 0; j < 8; j++) {
    int idx4 = tid + j * 256;
    int p = idx4 >> 7;
    int c = (idx4 & 127) * 4;
    const float* src = (c < 256) ? (g_hg + (size_t)sia[p] * 256 + c)
                                 : (g_hg + (size_t)sib[p] * 256 + (c - 256));
    *(float4*)&sp[p][c] = *(const float4*)src;
  }
  __syncthreads();
  int p = tid >> 4;
  int j0 = (tid & 15) * 4;
  float a0 = 0.f, a1 = 0.f, a2 = 0.f, a3 = 0.f;
  for (int k = 0; k < 512; k++) {
    float s = sp[p][k];
    float4 w = *(const float4*)(w1 + (size_t)k * 64 + j0);
    a0 += s * w.x; a1 += s * w.y; a2 += s * w.z; a3 += s * w.w;
  }
  a0 = fmaxf(a0 + b1[j0 + 0], 0.f);
  a1 = fmaxf(a1 + b1[j0 + 1], 0.f);
  a2 = fmaxf(a2 + b1[j0 + 2], 0.f);
  a3 = fmaxf(a3 + b1[j0 + 3], 0.f);
  float part = a0 * w2[j0 + 0] + a1 * w2[j0 + 1] + a2 * w2[j0 + 2] + a3 * w2[j0 + 3];
#pragma unroll
  for (int o = 1; o < 16; o <<= 1) part += __shfl_xor_sync(0xffffffffu, part, o);
  if ((tid & 15) == 0) {
    float z = part + b2[0];
    out[bp + p] = 1.f / (1.f + __expf(-z));
  }
}

// ---------------- launch ----------------
extern "C" void kernel_launch(void* const* d_in, const int* in_sizes, int n_in,
                              void* d_out, int out_size) {
  const float* x = (const float*)d_in[0];
  const int* edge_index = (const int*)d_in[1];
  const int* idx_A = (const int*)d_in[2];
  const int* idx_B = (const int*)d_in[3];
  const float* w_in = (const float*)d_in[4];
  const float* b_in = (const float*)d_in[5];
  const float* w_qkv = (const float*)d_in[6];
  const float* b_qkv = (const float*)d_in[7];
  const float* w_o = (const float*)d_in[8];
  const float* b_o = (const float*)d_in[9];
  const float* ln1_g = (const float*)d_in[10];
  const float* ln1_b = (const float*)d_in[11];
  const float* w_ff1 = (const float*)d_in[12];
  const float* b_ff1 = (const float*)d_in[13];
  const float* w_ff2 = (const float*)d_in[14];
  const float* b_ff2 = (const float*)d_in[15];
  const float* ln2_g = (const float*)d_in[16];
  const float* ln2_b = (const float*)d_in[17];
  const float* gat_w = (const float*)d_in[18];
  const float* att_src = (const float*)d_in[19];
  const float* att_dst = (const float*)d_in[20];
  const float* gat_bias = (const float*)d_in[21];
  const float* cls_w1 = (const float*)d_in[22];
  const float* cls_b1 = (const float*)d_in[23];
  const float* cls_w2 = (const float*)d_in[24];
  const float* cls_b2 = (const float*)d_in[25];
  float* out = (float*)d_out;

  void* p;
  cudaGetSymbolAddress(&p, g_h);   float* ph = (float*)p;
  cudaGetSymbolAddress(&p, g_qkv); float* pqkv = (float*)p;
  cudaGetSymbolAddress(&p, g_ctx); float* pctx = (float*)p;
  cudaGetSymbolAddress(&p, g_tmp); float* ptmp = (float*)p;
  cudaGetSymbolAddress(&p, g_h1);  float* ph1 = (float*)p;
  cudaGetSymbolAddress(&p, g_ff);  float* pff = (float*)p;
  cudaGetSymbolAddress(&p, g_h2);  float* ph2 = (float*)p;
  cudaGetSymbolAddress(&p, g_hw);  float* phw = (float*)p;

  mma_gemm<0><<<dim3(D_MODEL / 64, N_NODES / 128), 256>>>(
      x, w_in, b_in, ph, N_NODES, D_MODEL, D_INP);
  mma_gemm<0><<<dim3(3 * D_MODEL / 64, N_NODES / 128), 256>>>(
      ph, w_qkv, b_qkv, pqkv, N_NODES, 3 * D_MODEL, D_MODEL);
  attn_mma<<<dim3(N_NODES / 64, H_HEADS), 128>>>();
  mma_gemm<0><<<dim3(D_MODEL / 64, N_NODES / 128), 256>>>(
      pctx, w_o, b_o, ptmp, N_NODES, D_MODEL, D_MODEL);
  ln_res<<<N_NODES / 8, 256>>>(ph, ptmp, ln1_g, ln1_b, ph1);
  mma_gemm<1><<<dim3(FF_DIM / 64, N_NODES / 128), 256>>>(
      ph1, w_ff1, b_ff1, pff, N_NODES, FF_DIM, D_MODEL);
  mma_gemm<0><<<dim3(D_MODEL / 64, N_NODES / 128), 256>>>(
      pff, w_ff2, b_ff2, ptmp, N_NODES, D_MODEL, FF_DIM);
  ln_res<<<N_NODES / 8, 256>>>(ph1, ptmp, ln2_g, ln2_b, ph2);
  mma_gemm<0><<<dim3(H_HEADS * D_MODEL / 64, N_NODES / 128), 256>>>(
      ph2, gat_w, (const float*)nullptr, phw, N_NODES, H_HEADS * D_MODEL,
      D_MODEL);
  gat_dots<<<N_NODES, 256>>>(att_src, att_dst);
  csr_zero<<<(N_NODES + 255) / 256, 256>>>();
  csr_count<<<(EN_EDGES + 255) / 256, 256>>>(edge_index);
  csr_scan<<<1, 1024>>>();
  csr_fill<<<(EN_EDGES + 255) / 256, 256>>>(edge_index);
  gat_agg<<<N_NODES, 256>>>(gat_bias);
  classify<<<B_PAIRS / 16, 256>>>(cls_w1, cls_b1, cls_w2, cls_b2, idx_A, idx_B,
                                  out);
}

// round 5
// speedup vs baseline: 8.6941x; 1.1808x over previous
#include <cuda_runtime.h>
#include <math.h>
#include <stdint.h>

#define N_NODES 4096
#define E_EDGES 131072
#define EN_EDGES (E_EDGES + N_NODES)
#define D_INP 128
#define D_MODEL 256
#define H_HEADS 8
#define D_HEAD 32
#define FF_DIM 2048
#define B_PAIRS 16384

// ---------------- scratch (device globals; allocation-free) ----------------
__device__ __align__(256) float g_h[N_NODES * D_MODEL];
__device__ __align__(256) float g_qkv[N_NODES * 3 * D_MODEL];
__device__ __align__(256) float g_ctx[N_NODES * D_MODEL];
__device__ __align__(256) float g_tmp[N_NODES * D_MODEL];
__device__ __align__(256) float g_h1[N_NODES * D_MODEL];
__device__ __align__(256) float g_ff[N_NODES * FF_DIM];
__device__ __align__(256) float g_h2[N_NODES * D_MODEL];
__device__ __align__(256) float g_hw[N_NODES * H_HEADS * D_MODEL];
__device__ __align__(256) float g_asrc[N_NODES * H_HEADS];
__device__ __align__(256) float g_adst[N_NODES * H_HEADS];
__device__ __align__(256) float g_hg[N_NODES * D_MODEL];
__device__ int g_deg[N_NODES];
__device__ int g_off[N_NODES + 1];
__device__ int g_cursor[N_NODES];
__device__ int g_csrc[EN_EDGES];

// ---------------- helpers ----------------
__device__ __forceinline__ void mma_tf32(float* d, const uint32_t* a,
                                         const uint32_t* b) {
  asm volatile(
      "mma.sync.aligned.m16n8k8.row.col.f32.tf32.tf32.f32 "
      "{%0,%1,%2,%3}, {%4,%5,%6,%7}, {%8,%9}, {%0,%1,%2,%3};\n"
      : "+f"(d[0]), "+f"(d[1]), "+f"(d[2]), "+f"(d[3])
      : "r"(a[0]), "r"(a[1]), "r"(a[2]), "r"(a[3]), "r"(b[0]), "r"(b[1]));
}
__device__ __forceinline__ void cp_async16(void* s, const void* g) {
  uint32_t sa = (uint32_t)__cvta_generic_to_shared(s);
  asm volatile("cp.async.cg.shared.global [%0], [%1], 16;" ::"r"(sa), "l"(g)
               : "memory");
}
__device__ __forceinline__ void cp_commit() {
  asm volatile("cp.async.commit_group;" ::: "memory");
}
template <int Nleft>
__device__ __forceinline__ void cp_wait() {
  asm volatile("cp.async.wait_group %0;" ::"n"(Nleft) : "memory");
}

// ---------------- TF32 tensor-core GEMM: C[M,N] = A[M,K] @ B[K,N] ----------
// Tile 128x64x16, 256 threads (8 warps: 4 M x 2 N), warp tile 32x32.
// 2-stage cp.async pipeline; raw fp32 bits fed to mma.tf32 (truncation).
template <int RELU>
__global__ __launch_bounds__(256) void mma_gemm(
    const float* __restrict__ A, const float* __restrict__ B,
    const float* __restrict__ bias, float* __restrict__ C,
    int M, int Nn, int K) {
  __shared__ float As[2][128][20];
  __shared__ float Bs[2][16][72];
  int tid = threadIdx.x;
  int warp = tid >> 5, lane = tid & 31;
  int gid = lane >> 2, tig = lane & 3;
  int bm = blockIdx.y * 128, bn = blockIdx.x * 64;
  int wm = (warp & 3) * 32;
  int wn = (warp >> 2) * 32;

  float acc[2][4][4];
#pragma unroll
  for (int t = 0; t < 2; t++)
#pragma unroll
    for (int u = 0; u < 4; u++)
#pragma unroll
      for (int i = 0; i < 4; i++) acc[t][u][i] = 0.f;

  int ar = tid >> 1, ac = (tid & 1) * 8;
  int br = tid >> 4, bc = (tid & 15) * 4;
  const float* Aptr = A + (size_t)(bm + ar) * K + ac;
  const float* Bptr = B + (size_t)br * Nn + bn + bc;

#define GEMM_LOAD(s, k0)                                  \
  do {                                                    \
    cp_async16(&As[s][ar][ac], Aptr + (k0));              \
    cp_async16(&As[s][ar][ac + 4], Aptr + (k0) + 4);      \
    cp_async16(&Bs[s][br][bc], Bptr + (size_t)(k0) * Nn); \
    cp_commit();                                          \
  } while (0)

  GEMM_LOAD(0, 0);
  if (K > 16) GEMM_LOAD(1, 16);

  int s = 0;
  for (int k0 = 0; k0 < K; k0 += 16) {
    if (k0 + 16 < K) cp_wait<1>();
    else cp_wait<0>();
    __syncthreads();
#pragma unroll
    for (int ks = 0; ks < 16; ks += 8) {
      uint32_t af[2][4], bf[4][2];
#pragma unroll
      for (int t = 0; t < 2; t++) {
        int row = wm + t * 16 + gid;
        af[t][0] = __float_as_uint(As[s][row][ks + tig]);
        af[t][1] = __float_as_uint(As[s][row + 8][ks + tig]);
        af[t][2] = __float_as_uint(As[s][row][ks + tig + 4]);
        af[t][3] = __float_as_uint(As[s][row + 8][ks + tig + 4]);
      }
#pragma unroll
      for (int u = 0; u < 4; u++) {
        int col = wn + u * 8 + gid;
        bf[u][0] = __float_as_uint(Bs[s][ks + tig][col]);
        bf[u][1] = __float_as_uint(Bs[s][ks + tig + 4][col]);
      }
#pragma unroll
      for (int t = 0; t < 2; t++)
#pragma unroll
        for (int u = 0; u < 4; u++) mma_tf32(acc[t][u], af[t], bf[u]);
    }
    __syncthreads();
    if (k0 + 32 < K) GEMM_LOAD(s, k0 + 32);
    s ^= 1;
  }
#undef GEMM_LOAD

#pragma unroll
  for (int t = 0; t < 2; t++) {
#pragma unroll
    for (int u = 0; u < 4; u++) {
      int r = bm + wm + t * 16 + gid;
      int c = bn + wn + u * 8 + tig * 2;
      float b0 = bias ? bias[c] : 0.f;
      float b1 = bias ? bias[c + 1] : 0.f;
      float2 o0 = {acc[t][u][0] + b0, acc[t][u][1] + b1};
      float2 o1 = {acc[t][u][2] + b0, acc[t][u][3] + b1};
      if (RELU) {
        o0.x = fmaxf(o0.x, 0.f); o0.y = fmaxf(o0.y, 0.f);
        o1.x = fmaxf(o1.x, 0.f); o1.y = fmaxf(o1.y, 0.f);
      }
      *(float2*)(C + (size_t)r * Nn + c) = o0;
      *(float2*)(C + (size_t)(r + 8) * Nn + c) = o1;
    }
  }
}

// ---------------- TF32 tensor-core flash attention ----------------
// grid (N/64, H), block 128 (4 warps x 16 q-rows). Tiles: 64q x 64k, DH=32.
// K double-buffered (cp.async, 1 tile ahead); V single-buffered, prefetched
// right after the PV that consumes the previous V tile.
// Conflict-free strides mod 32: Ks 36->4, Vs 40->8, Ps 68->4.
// Static smem: 2*64*36*4 + 64*40*4 + 64*68*4 = 46080 bytes (< 48KB).
__global__ __launch_bounds__(128) void attn_mma() {
  __shared__ float Ks[2][64][36];
  __shared__ float Vs[64][40];
  __shared__ float Ps[64][68];
  int tid = threadIdx.x;
  int warp = tid >> 5, lane = tid & 31;
  int gid = lane >> 2, tig = lane & 3;
  int h = blockIdx.y;
  int qb = blockIdx.x * 64;
  int r0 = warp * 16 + gid;
  const float scale = 0.17677669529663687f;  // 1/sqrt(32)

#define K_LOAD(s, kt)                                                     \
  do {                                                                    \
    _Pragma("unroll") for (int j = 0; j < 4; j++) {                       \
      int idx = tid + j * 128;                                            \
      int r = idx >> 3, c4 = (idx & 7) * 4;                               \
      cp_async16(&Ks[s][r][c4],                                           \
                 g_qkv + (size_t)((kt) + r) * 768 + 256 + h * 32 + c4);   \
    }                                                                     \
    cp_commit();                                                          \
  } while (0)
#define V_LOAD(kt)                                                        \
  do {                                                                    \
    _Pragma("unroll") for (int j = 0; j < 4; j++) {                       \
      int idx = tid + j * 128;                                            \
      int r = idx >> 3, c4 = (idx & 7) * 4;                               \
      cp_async16(&Vs[r][c4],                                              \
                 g_qkv + (size_t)((kt) + r) * 768 + 512 + h * 32 + c4);   \
    }                                                                     \
    cp_commit();                                                          \
  } while (0)

  // prefetch: K0, V0, K64 (in-order groups)
  K_LOAD(0, 0);
  V_LOAD(0);
  K_LOAD(1, 64);

  // ---- stage scaled Q tile (64x32) through Ps, build fragments
#pragma unroll
  for (int j = 0; j < 4; j++) {
    int idx = tid + j * 128;
    int r = idx >> 3, c4 = (idx & 7) * 4;
    float4 v = *(const float4*)(g_qkv + (size_t)(qb + r) * 768 + h * 32 + c4);
    Ps[r][c4 + 0] = v.x * scale;
    Ps[r][c4 + 1] = v.y * scale;
    Ps[r][c4 + 2] = v.z * scale;
    Ps[r][c4 + 3] = v.w * scale;
  }
  __syncthreads();
  uint32_t qf[4][4];
#pragma unroll
  for (int ks = 0; ks < 4; ks++) {
    qf[ks][0] = __float_as_uint(Ps[r0][ks * 8 + tig]);
    qf[ks][1] = __float_as_uint(Ps[r0 + 8][ks * 8 + tig]);
    qf[ks][2] = __float_as_uint(Ps[r0][ks * 8 + tig + 4]);
    qf[ks][3] = __float_as_uint(Ps[r0 + 8][ks * 8 + tig + 4]);
  }
  __syncthreads();  // Ps will be overwritten with P values below

  float m0 = -1e30f, m1 = -1e30f, Z0 = 0.f, Z1 = 0.f;
  float oacc[4][4];
#pragma unroll
  for (int u = 0; u < 4; u++)
#pragma unroll
    for (int i = 0; i < 4; i++) oacc[u][i] = 0.f;

  int s = 0;
  for (int kt = 0; kt < N_NODES; kt += 64) {
    // need K(kt) and V(kt); only K(kt+64) may remain in flight
    if (kt + 64 < N_NODES) cp_wait<1>();
    else cp_wait<0>();
    __syncthreads();

    // ---- S = Q @ K^T (scaled)
    float sc[8][4];
#pragma unroll
    for (int u = 0; u < 8; u++) {
      sc[u][0] = sc[u][1] = sc[u][2] = sc[u][3] = 0.f;
#pragma unroll
      for (int ks = 0; ks < 4; ks++) {
        uint32_t bf[2];
        bf[0] = __float_as_uint(Ks[s][u * 8 + gid][ks * 8 + tig]);
        bf[1] = __float_as_uint(Ks[s][u * 8 + gid][ks * 8 + tig + 4]);
        mma_tf32(sc[u], qf[ks], bf);
      }
    }
    // ---- row max
    float t0 = -1e30f, t1 = -1e30f;
#pragma unroll
    for (int u = 0; u < 8; u++) {
      t0 = fmaxf(t0, fmaxf(sc[u][0], sc[u][1]));
      t1 = fmaxf(t1, fmaxf(sc[u][2], sc[u][3]));
    }
#pragma unroll
    for (int o = 1; o < 4; o <<= 1) {
      t0 = fmaxf(t0, __shfl_xor_sync(0xffffffffu, t0, o));
      t1 = fmaxf(t1, __shfl_xor_sync(0xffffffffu, t1, o));
    }
    float mn0 = fmaxf(m0, t0), mn1 = fmaxf(m1, t1);
    float f0 = __expf(m0 - mn0), f1 = __expf(m1 - mn1);
    m0 = mn0; m1 = mn1;
    // ---- P = exp(S - m) -> Ps; row sums
    float l0 = 0.f, l1 = 0.f;
#pragma unroll
    for (int u = 0; u < 8; u++) {
      float p00 = __expf(sc[u][0] - mn0);
      float p01 = __expf(sc[u][1] - mn0);
      float p10 = __expf(sc[u][2] - mn1);
      float p11 = __expf(sc[u][3] - mn1);
      l0 += p00 + p01; l1 += p10 + p11;
      float2 w0 = {p00, p01};
      float2 w1 = {p10, p11};
      *(float2*)&Ps[r0][u * 8 + tig * 2] = w0;
      *(float2*)&Ps[r0 + 8][u * 8 + tig * 2] = w1;
    }
#pragma unroll
    for (int o = 1; o < 4; o <<= 1) {
      l0 += __shfl_xor_sync(0xffffffffu, l0, o);
      l1 += __shfl_xor_sync(0xffffffffu, l1, o);
    }
    Z0 = Z0 * f0 + l0;
    Z1 = Z1 * f1 + l1;
#pragma unroll
    for (int u = 0; u < 4; u++) {
      oacc[u][0] *= f0; oacc[u][1] *= f0;
      oacc[u][2] *= f1; oacc[u][3] *= f1;
    }
    __syncwarp();  // Ps rows are warp-private (16-row slab per warp)

    // ---- O += P @ V
#pragma unroll
    for (int ks = 0; ks < 8; ks++) {
      uint32_t af[4];
      af[0] = __float_as_uint(Ps[r0][ks * 8 + tig]);
      af[1] = __float_as_uint(Ps[r0 + 8][ks * 8 + tig]);
      af[2] = __float_as_uint(Ps[r0][ks * 8 + tig + 4]);
      af[3] = __float_as_uint(Ps[r0 + 8][ks * 8 + tig + 4]);
#pragma unroll
      for (int u = 0; u < 4; u++) {
        uint32_t bf[2];
        bf[0] = __float_as_uint(Vs[ks * 8 + tig][u * 8 + gid]);
        bf[1] = __float_as_uint(Vs[ks * 8 + tig + 4][u * 8 + gid]);
        mma_tf32(oacc[u], af, bf);
      }
    }
    __syncthreads();  // everyone done with Vs / Ks[s] before overwrite
    if (kt + 64 < N_NODES) V_LOAD(kt + 64);
    if (kt + 128 < N_NODES) K_LOAD(s, kt + 128);
    s ^= 1;
  }
#undef K_LOAD
#undef V_LOAD

  float i0 = 1.f / Z0, i1 = 1.f / Z1;
#pragma unroll
  for (int u = 0; u < 4; u++) {
    float2 o0 = {oacc[u][0] * i0, oacc[u][1] * i0};
    float2 o1 = {oacc[u][2] * i1, oacc[u][3] * i1};
    int c = h * 32 + u * 8 + tig * 2;
    *(float2*)(g_ctx + (size_t)(qb + r0) * 256 + c) = o0;
    *(float2*)(g_ctx + (size_t)(qb + r0 + 8) * 256 + c) = o1;
  }
}

// ---------------- residual + LayerNorm ----------------
__global__ __launch_bounds__(256) void ln_res(const float* __restrict__ a,
                                              const float* __restrict__ b,
                                              const float* __restrict__ gam,
                                              const float* __restrict__ bet,
                                              float* __restrict__ out) {
  int w = threadIdx.x >> 5, lane = threadIdx.x & 31;
  int row = blockIdx.x * 8 + w;
  float x[8];
  float s = 0.f;
#pragma unroll
  for (int i = 0; i < 8; i++) {
    int d = lane + i * 32;
    x[i] = a[(size_t)row * 256 + d] + b[(size_t)row * 256 + d];
    s += x[i];
  }
#pragma unroll
  for (int o = 16; o; o >>= 1) s += __shfl_xor_sync(0xffffffffu, s, o);
  float mean = s * (1.f / 256.f);
  float v = 0.f;
#pragma unroll
  for (int i = 0; i < 8; i++) {
    float t = x[i] - mean;
    v += t * t;
  }
#pragma unroll
  for (int o = 16; o; o >>= 1) v += __shfl_xor_sync(0xffffffffu, v, o);
  float r = rsqrtf(v * (1.f / 256.f) + 1e-5f);
#pragma unroll
  for (int i = 0; i < 8; i++) {
    int d = lane + i * 32;
    out[(size_t)row * 256 + d] = (x[i] - mean) * r * gam[d] + bet[d];
  }
}

// ---------------- GAT attention dot products ----------------
__global__ __launch_bounds__(256) void gat_dots(const float* __restrict__ att_src,
                                                const float* __restrict__ att_dst) {
  int n = blockIdx.x;
  int w = threadIdx.x >> 5, lane = threadIdx.x & 31;
  const float* row = g_hw + (size_t)n * 2048 + w * 256;
  float s1 = 0.f, s2 = 0.f;
#pragma unroll
  for (int i = 0; i < 8; i++) {
    int d = lane + i * 32;
    float v = row[d];
    s1 += v * att_src[w * 256 + d];
    s2 += v * att_dst[w * 256 + d];
  }
#pragma unroll
  for (int o = 16; o; o >>= 1) {
    s1 += __shfl_xor_sync(0xffffffffu, s1, o);
    s2 += __shfl_xor_sync(0xffffffffu, s2, o);
  }
  if (!lane) {
    g_asrc[n * 8 + w] = s1;
    g_adst[n * 8 + w] = s2;
  }
}

// ---------------- CSR build ----------------
__global__ void csr_zero() {
  int i = blockIdx.x * 256 + threadIdx.x;
  if (i < N_NODES) g_deg[i] = 0;
}
__global__ void csr_count(const int* __restrict__ ei) {
  int i = blockIdx.x * 256 + threadIdx.x;
  if (i >= EN_EDGES) return;
  int d = (i < E_EDGES) ? ei[E_EDGES + i] : (i - E_EDGES);
  atomicAdd(&g_deg[d], 1);
}
__global__ __launch_bounds__(1024) void csr_scan() {
  __shared__ int s[1024];
  int tid = threadIdx.x;
  int v0 = g_deg[tid * 4 + 0], v1 = g_deg[tid * 4 + 1];
  int v2 = g_deg[tid * 4 + 2], v3 = g_deg[tid * 4 + 3];
  int tsum = v0 + v1 + v2 + v3;
  s[tid] = tsum;
  __syncthreads();
  for (int o = 1; o < 1024; o <<= 1) {
    int t = (tid >= o) ? s[tid - o] : 0;
    __syncthreads();
    s[tid] += t;
    __syncthreads();
  }
  int excl = tid ? s[tid - 1] : 0;
  int o0 = excl, o1 = o0 + v0, o2 = o1 + v1, o3 = o2 + v2;
  g_off[tid * 4 + 0] = o0; g_cursor[tid * 4 + 0] = o0;
  g_off[tid * 4 + 1] = o1; g_cursor[tid * 4 + 1] = o1;
  g_off[tid * 4 + 2] = o2; g_cursor[tid * 4 + 2] = o2;
  g_off[tid * 4 + 3] = o3; g_cursor[tid * 4 + 3] = o3;
  if (tid == 1023) g_off[N_NODES] = excl + tsum;
}
__global__ void csr_fill(const int* __restrict__ ei) {
  int i = blockIdx.x * 256 + threadIdx.x;
  if (i >= EN_EDGES) return;
  int srcv = (i < E_EDGES) ? ei[i] : (i - E_EDGES);
  int dstv = (i < E_EDGES) ? ei[E_EDGES + i] : (i - E_EDGES);
  int pos = atomicAdd(&g_cursor[dstv], 1);
  g_csrc[pos] = srcv;
}

// ---------------- GAT aggregation ----------------
__global__ __launch_bounds__(256) void gat_agg(const float* __restrict__ gat_bias) {
  int n = blockIdx.x, tid = threadIdx.x;
  __shared__ int ssrc[256];
  __shared__ float se[256 * 8];
  __shared__ float sm[8], sz[8], sfac[8], sadst[8];
  __shared__ float sred[8 * 32];

  int start = g_off[n], end = g_off[n + 1];
  if (tid < 8) {
    sm[tid] = -1e30f;
    sz[tid] = 0.f;
    sadst[tid] = g_adst[n * 8 + tid];
  }
  float acc[8];
#pragma unroll
  for (int i = 0; i < 8; i++) acc[i] = 0.f;
  __syncthreads();

  for (int cs = start; cs < end; cs += 256) {
    int cnt = min(256, end - cs);
    if (tid < cnt) ssrc[tid] = g_csrc[cs + tid];
    __syncthreads();
#pragma unroll
    for (int j = 0; j < 8; j++) {
      int idx = tid + j * 256;
      int eidx = idx >> 3, hh = idx & 7;
      if (eidx < cnt) {
        float v = g_asrc[ssrc[eidx] * 8 + hh] + sadst[hh];
        se[idx] = (v > 0.f) ? v : 0.2f * v;
      }
    }
    __syncthreads();
    int h = tid & 7, gg = tid >> 3;
    float mx = -1e30f;
    for (int e = gg; e < cnt; e += 32) mx = fmaxf(mx, se[e * 8 + h]);
    sred[h * 32 + gg] = mx;
    __syncthreads();
    if (tid < 8) {
      float m2 = -1e30f;
      for (int g2 = 0; g2 < 32; g2++) m2 = fmaxf(m2, sred[tid * 32 + g2]);
      float mold = sm[tid];
      float mnew = fmaxf(mold, m2);
      sfac[tid] = __expf(mold - mnew);
      sm[tid] = mnew;
      sz[tid] *= sfac[tid];
    }
    __syncthreads();
#pragma unroll
    for (int i = 0; i < 8; i++) acc[i] *= sfac[i];
    float sum = 0.f;
    for (int e = gg; e < cnt; e += 32) {
      float p = __expf(se[e * 8 + h] - sm[h]);
      se[e * 8 + h] = p;
      sum += p;
    }
    sred[h * 32 + gg] = sum;
    __syncthreads();
    if (tid < 8) {
      float s2 = 0.f;
      for (int g2 = 0; g2 < 32; g2++) s2 += sred[tid * 32 + g2];
      sz[tid] += s2;
    }
    __syncthreads();
    for (int e = 0; e < cnt; e++) {
      const float* row = g_hw + (size_t)ssrc[e] * 2048;
#pragma unroll
      for (int hh = 0; hh < 8; hh++)
        acc[hh] += se[e * 8 + hh] * row[hh * 256 + tid];
    }
    __syncthreads();
  }
  float r = 0.f;
#pragma unroll
  for (int hh = 0; hh < 8; hh++) r += acc[hh] / (sz[hh] + 1e-16f);
  g_hg[(size_t)n * 256 + tid] = r * 0.125f + gat_bias[tid];
}

// ---------------- fused classifier ----------------
__global__ __launch_bounds__(256) void classify(
    const float* __restrict__ w1, const float* __restrict__ b1,
    const float* __restrict__ w2, const float* __restrict__ b2,
    const int* __restrict__ iA, const int* __restrict__ iB,
    float* __restrict__ out) {
  __shared__ float sp[16][512];
  __shared__ int sia[16], sib[16];
  int tid = threadIdx.x;
  int bp = blockIdx.x * 16;
  if (tid < 16) sia[tid] = iA[bp + tid];
  else if (tid < 32) sib[tid - 16] = iB[bp + tid - 16];
  __syncthreads();
#pragma unroll
  for (int j = 0; j < 8; j++) {
    int idx4 = tid + j * 256;
    int p = idx4 >> 7;
    int c = (idx4 & 127) * 4;
    const float* src = (c < 256) ? (g_hg + (size_t)sia[p] * 256 + c)
                                 : (g_hg + (size_t)sib[p] * 256 + (c - 256));
    *(float4*)&sp[p][c] = *(const float4*)src;
  }
  __syncthreads();
  int p = tid >> 4;
  int j0 = (tid & 15) * 4;
  float a0 = 0.f, a1 = 0.f, a2 = 0.f, a3 = 0.f;
  for (int k = 0; k < 512; k++) {
    float s = sp[p][k];
    float4 w = *(const float4*)(w1 + (size_t)k * 64 + j0);
    a0 += s * w.x; a1 += s * w.y; a2 += s * w.z; a3 += s * w.w;
  }
  a0 = fmaxf(a0 + b1[j0 + 0], 0.f);
  a1 = fmaxf(a1 + b1[j0 + 1], 0.f);
  a2 = fmaxf(a2 + b1[j0 + 2], 0.f);
  a3 = fmaxf(a3 + b1[j0 + 3], 0.f);
  float part = a0 * w2[j0 + 0] + a1 * w2[j0 + 1] + a2 * w2[j0 + 2] + a3 * w2[j0 + 3];
#pragma unroll
  for (int o = 1; o < 16; o <<= 1) part += __shfl_xor_sync(0xffffffffu, part, o);
  if ((tid & 15) == 0) {
    float z = part + b2[0];
    out[bp + p] = 1.f / (1.f + __expf(-z));
  }
}

// ---------------- launch ----------------
extern "C" void kernel_launch(void* const* d_in, const int* in_sizes, int n_in,
                              void* d_out, int out_size) {
  const float* x = (const float*)d_in[0];
  const int* edge_index = (const int*)d_in[1];
  const int* idx_A = (const int*)d_in[2];
  const int* idx_B = (const int*)d_in[3];
  const float* w_in = (const float*)d_in[4];
  const float* b_in = (const float*)d_in[5];
  const float* w_qkv = (const float*)d_in[6];
  const float* b_qkv = (const float*)d_in[7];
  const float* w_o = (const float*)d_in[8];
  const float* b_o = (const float*)d_in[9];
  const float* ln1_g = (const float*)d_in[10];
  const float* ln1_b = (const float*)d_in[11];
  const float* w_ff1 = (const float*)d_in[12];
  const float* b_ff1 = (const float*)d_in[13];
  const float* w_ff2 = (const float*)d_in[14];
  const float* b_ff2 = (const float*)d_in[15];
  const float* ln2_g = (const float*)d_in[16];
  const float* ln2_b = (const float*)d_in[17];
  const float* gat_w = (const float*)d_in[18];
  const float* att_src = (const float*)d_in[19];
  const float* att_dst = (const float*)d_in[20];
  const float* gat_bias = (const float*)d_in[21];
  const float* cls_w1 = (const float*)d_in[22];
  const float* cls_b1 = (const float*)d_in[23];
  const float* cls_w2 = (const float*)d_in[24];
  const float* cls_b2 = (const float*)d_in[25];
  float* out = (float*)d_out;

  void* p;
  cudaGetSymbolAddress(&p, g_h);   float* ph = (float*)p;
  cudaGetSymbolAddress(&p, g_qkv); float* pqkv = (float*)p;
  cudaGetSymbolAddress(&p, g_ctx); float* pctx = (float*)p;
  cudaGetSymbolAddress(&p, g_tmp); float* ptmp = (float*)p;
  cudaGetSymbolAddress(&p, g_h1);  float* ph1 = (float*)p;
  cudaGetSymbolAddress(&p, g_ff);  float* pff = (float*)p;
  cudaGetSymbolAddress(&p, g_h2);  float* ph2 = (float*)p;
  cudaGetSymbolAddress(&p, g_hw);  float* phw = (float*)p;

  mma_gemm<0><<<dim3(D_MODEL / 64, N_NODES / 128), 256>>>(
      x, w_in, b_in, ph, N_NODES, D_MODEL, D_INP);
  mma_gemm<0><<<dim3(3 * D_MODEL / 64, N_NODES / 128), 256>>>(
      ph, w_qkv, b_qkv, pqkv, N_NODES, 3 * D_MODEL, D_MODEL);
  attn_mma<<<dim3(N_NODES / 64, H_HEADS), 128>>>();
  mma_gemm<0><<<dim3(D_MODEL / 64, N_NODES / 128), 256>>>(
      pctx, w_o, b_o, ptmp, N_NODES, D_MODEL, D_MODEL);
  ln_res<<<N_NODES / 8, 256>>>(ph, ptmp, ln1_g, ln1_b, ph1);
  mma_gemm<1><<<dim3(FF_DIM / 64, N_NODES / 128), 256>>>(
      ph1, w_ff1, b_ff1, pff, N_NODES, FF_DIM, D_MODEL);
  mma_gemm<0><<<dim3(D_MODEL / 64, N_NODES / 128), 256>>>(
      pff, w_ff2, b_ff2, ptmp, N_NODES, D_MODEL, FF_DIM);
  ln_res<<<N_NODES / 8, 256>>>(ph1, ptmp, ln2_g, ln2_b, ph2);
  mma_gemm<0><<<dim3(H_HEADS * D_MODEL / 64, N_NODES / 128), 256>>>(
      ph2, gat_w, (const float*)nullptr, phw, N_NODES, H_HEADS * D_MODEL,
      D_MODEL);
  gat_dots<<<N_NODES, 256>>>(att_src, att_dst);
  csr_zero<<<(N_NODES + 255) / 256, 256>>>();
  csr_count<<<(EN_EDGES + 255) / 256, 256>>>(edge_index);
  csr_scan<<<1, 1024>>>();
  csr_fill<<<(EN_EDGES + 255) / 256, 256>>>(edge_index);
  gat_agg<<<N_NODES, 256>>>(gat_bias);
  classify<<<B_PAIRS / 16, 256>>>(cls_w1, cls_b1, cls_w2, cls_b2, idx_A, idx_B,
                                  out);
}